// round 10
// baseline (speedup 1.0000x reference)
#include <cuda_runtime.h>
#include <cuda_fp16.h>
#include <cstdint>

#define Bv 32
#define Tv 1500
#define Ev 1024
#define Hv 8
#define DKv 128
#define DVv 128
#define Dv 1024
#define SCALING 0.088388347648318447f  // 1/sqrt(128)
#define TCHUNK 12

// Scratch (no allocations allowed)
__device__ float g_q[Bv * Hv * DKv];            // tanh(dec_z@Wq + bq)
__device__ float g_c[Bv * Hv * DVv];            // u @ Wv
__device__ float g_up[TCHUNK * Bv * Hv * Ev];   // u partials over t-chunks
__device__ __half g_enc16[(size_t)Bv * Tv * Ev];   // enc in fp16 (98.3 MB)
__device__ __half g_wkT16[(size_t)Hv * DKv * Ev];  // Wk^T in fp16: [h][n][e]

// ---------------------------------------------------------------------------
// PTX helpers (sm_80-level only; tcgen05 is rejected by this harness target)
// ---------------------------------------------------------------------------
__device__ __forceinline__ uint32_t smem_u32(const void* p) {
    uint32_t a;
    asm("{ .reg .u64 t; cvta.to.shared.u64 t, %1; cvt.u32.u64 %0, t; }" : "=r"(a) : "l"(p));
    return a;
}
#define CP16(sm, gm, sz) \
    asm volatile("cp.async.cg.shared.global [%0], [%1], 16, %2;" ::"r"(sm), "l"(gm), "r"(sz) : "memory")
#define CP_COMMIT() asm volatile("cp.async.commit_group;" ::: "memory")
#define CP_WAIT2() asm volatile("cp.async.wait_group 2;" ::: "memory")
#define LDSM4(r0, r1, r2, r3, a)                                             \
    asm volatile("ldmatrix.sync.aligned.m8n8.x4.shared.b16 {%0,%1,%2,%3}, [%4];" \
                 : "=r"(r0), "=r"(r1), "=r"(r2), "=r"(r3) : "r"(a))

__device__ __forceinline__ void mma_f16(float* d, uint32_t a0, uint32_t a1, uint32_t a2,
                                        uint32_t a3, uint32_t b0, uint32_t b1) {
    asm volatile(
        "mma.sync.aligned.m16n8k16.row.col.f32.f16.f16.f32 "
        "{%0,%1,%2,%3}, {%4,%5,%6,%7}, {%8,%9}, {%0,%1,%2,%3};"
        : "+f"(d[0]), "+f"(d[1]), "+f"(d[2]), "+f"(d[3])
        : "r"(a0), "r"(a1), "r"(a2), "r"(a3), "r"(b0), "r"(b1));
}
__device__ __forceinline__ uint32_t sw128(uint32_t o) { return o ^ ((o >> 3) & 0x70); }

// ---------------------------------------------------------------------------
// Length read with dtype sniff (int64 declared, int32 in practice)
// ---------------------------------------------------------------------------
__device__ __forceinline__ int get_len(const int* __restrict__ L, int b) {
    bool is64 = (L[1] == 0);
    return is64 ? L[2 * b] : L[b];
}

// ---------------------------------------------------------------------------
// enc -> fp16 (round-to-nearest), clipped to ceil128(len) rows per batch.
// (Unwritten rows stay zero — skipped-tile reads see finite values.)
// ---------------------------------------------------------------------------
__global__ __launch_bounds__(256) void enc16_kernel(const float* __restrict__ enc,
                                                    const int* __restrict__ lens) {
    size_t base = ((size_t)blockIdx.x * 256 + threadIdx.x) * 8;
    int t = (int)((base / Ev) % Tv);
    int b = (int)(base / ((size_t)Ev * Tv));
    int len = get_len(lens, b);
    if (t >= ((len + 127) & ~127)) return;
    float4 v0 = *(const float4*)(enc + base);
    float4 v1 = *(const float4*)(enc + base + 4);
    __half2 h[4];
    h[0] = __floats2half2_rn(v0.x, v0.y);
    h[1] = __floats2half2_rn(v0.z, v0.w);
    h[2] = __floats2half2_rn(v1.x, v1.y);
    h[3] = __floats2half2_rn(v1.z, v1.w);
    *(uint4*)(g_enc16 + base) = *(uint4*)h;
}

// ---------------------------------------------------------------------------
// wkT16[h][n][e] = fp16(Wk[h][e][n])
// ---------------------------------------------------------------------------
__global__ __launch_bounds__(256) void wkT16_kernel(const float* __restrict__ Wk) {
    __shared__ float tile[32][33];
    int e0 = blockIdx.x * 32, n0 = blockIdx.y * 32, h = blockIdx.z;
    int tx = threadIdx.x & 31, ty = threadIdx.x >> 5;
    for (int i = ty; i < 32; i += 8)
        tile[i][tx] = Wk[((size_t)h * Ev + e0 + i) * DKv + n0 + tx];
    __syncthreads();
    for (int i = ty; i < 32; i += 8)
        g_wkT16[((size_t)h * DKv + n0 + i) * Ev + e0 + tx] = __float2half_rn(tile[tx][i]);
}

// ---------------------------------------------------------------------------
// q[b,h,k] = tanh(dec_z[b,:]·Wq[h,:,k] + bq[h,k]); 4 accumulators for MLP.
// ---------------------------------------------------------------------------
__global__ __launch_bounds__(128) void q_kernel(const float* __restrict__ dec_z,
                                                const float* __restrict__ Wq,
                                                const float* __restrict__ bq) {
    int h = blockIdx.x, b = blockIdx.y;
    int k = threadIdx.x;
    __shared__ float zs[Dv];
    for (int i = k; i < Dv; i += 128) zs[i] = dec_z[b * Dv + i];
    __syncthreads();
    const float* W = Wq + (size_t)h * Dv * DKv + k;
    float a[4] = {0.f, 0.f, 0.f, 0.f};
#pragma unroll 4
    for (int d = 0; d < Dv; d += 4) {
        a[0] += zs[d] * W[(size_t)d * DKv];
        a[1] += zs[d + 1] * W[(size_t)(d + 1) * DKv];
        a[2] += zs[d + 2] * W[(size_t)(d + 2) * DKv];
        a[3] += zs[d + 3] * W[(size_t)(d + 3) * DKv];
    }
    g_q[(b * Hv + h) * DKv + k] = tanhf(bq[h * DKv + k] + (a[0] + a[1]) + (a[2] + a[3]));
}

// ---------------------------------------------------------------------------
// e[b,h,t]: fp16 m16n8k16 GEMM, TWO 128-t tiles per CTA sharing B fragments.
// Per kk: 4 B-LDSM + 4 A-LDSM for 32 MMA (ratio 4.0 vs 2.67). 1 CTA/SM,
// 4-stage depth-3 cp.async ring (A0/A1/B per stage). t0 >= len pairs exit.
// ---------------------------------------------------------------------------
#define ECH 64                  // K halves per stage (128 B per row)
#define ENCH (Ev / ECH)         // 16 chunks
#define EST 16384               // one 128x128B tile
#define STG (3 * EST)           // stage: A0 + A1 + B = 49152
#define NSTG 4
#define OFF_QS (NSTG * STG)     // 196608
#define OFF_RED (OFF_QS + 512)
#define E_SMEM (OFF_RED + 1024) // 198144 (1 CTA/SM)

__global__ __launch_bounds__(256) void e_tc_kernel(float* __restrict__ ebuf,
                                                   const int* __restrict__ lens) {
    extern __shared__ __align__(16) char dsm[];
    float* qs = (float*)(dsm + OFF_QS);
    float* red = (float*)(dsm + OFF_RED);  // [2][128]

    int tid = threadIdx.x, wid = tid >> 5, lane = tid & 31;
    int h = blockIdx.x, pair = blockIdx.y, b = blockIdx.z;
    int t0 = pair * 256;
    int len = get_len(lens, b);
    if (t0 >= len) return;  // dead pair: softmax writes 0 over this range

    int wm = wid & 3, wn = wid >> 2;
    int lane4 = lane >> 2, laneq = lane & 3;

    if (tid < DKv) qs[tid] = g_q[(b * Hv + h) * DKv + tid];

    const __half* A = g_enc16 + (size_t)b * Tv * Ev;
    const __half* Wt = g_wkT16 + (size_t)h * DKv * Ev;

    uint32_t base = smem_u32(dsm);

    // Store-side: per thread 4 (row,seg) slots; offsets in elements.
    uint32_t swz[4];
    size_t offA0[4], offB[4];
    uint32_t szA0[4], szA1[4];
#pragma unroll
    for (int r = 0; r < 4; r++) {
        int idx = r * 256 + tid;
        int row = idx >> 3, seg = idx & 7;
        swz[r] = sw128(row * 128 + seg * 16);
        szA0[r] = (t0 + row < Tv) ? 16u : 0u;
        szA1[r] = (t0 + 128 + row < Tv) ? 16u : 0u;
        offA0[r] = (size_t)(t0 + row) * Ev + seg * 8;
        offB[r] = (size_t)row * Ev + seg * 8;
    }

    auto issue = [&](int c, int s) {
        int k0 = c * ECH;
        uint32_t st = base + s * STG;
#pragma unroll
        for (int r = 0; r < 4; r++) CP16(st + swz[r], A + offA0[r] + k0, szA0[r]);
#pragma unroll
        for (int r = 0; r < 4; r++)
            CP16(st + EST + swz[r], A + offA0[r] + (size_t)128 * Ev + k0, szA1[r]);
#pragma unroll
        for (int r = 0; r < 4; r++) CP16(st + 2 * EST + swz[r], Wt + offB[r] + k0, 16u);
        CP_COMMIT();
    };

    // ldmatrix-side row terms + swizzle masks
    int rowAl = (lane & 7) + ((lane >> 3) & 1) * 8;
    int colAl = ((lane >> 4) & 1) * 16;
    int rowBl = (lane & 7) + ((lane >> 4) & 1) * 8;
    int colBl = ((lane >> 3) & 1) * 16;
    uint32_t aRow[2], aMask[2];
#pragma unroll
    for (int ms = 0; ms < 2; ms++) {
        int row = wm * 32 + ms * 16 + rowAl;
        aRow[ms] = row * 128;
        aMask[ms] = (row & 7) << 4;
    }
    uint32_t bRow[4], bMask[4];
#pragma unroll
    for (int pp = 0; pp < 4; pp++) {
        int row = wn * 64 + pp * 16 + rowBl;
        bRow[pp] = row * 128;
        bMask[pp] = (row & 7) << 4;
    }

    float d0[2][8][4], d1[2][8][4];
#pragma unroll
    for (int ms = 0; ms < 2; ms++)
#pragma unroll
        for (int ns = 0; ns < 8; ns++)
#pragma unroll
            for (int j = 0; j < 4; j++) { d0[ms][ns][j] = 0.f; d1[ms][ns][j] = 0.f; }

    issue(0, 0);
    issue(1, 1);
    issue(2, 2);

    for (int c = 0; c < ENCH; c++) {
        int s = c & (NSTG - 1);
        CP_WAIT2();      // <=2 groups pending => group c complete
        __syncthreads(); // all warps done with stage being refilled below
        if (c + 3 < ENCH) issue(c + 3, (c + 3) & (NSTG - 1));
        uint32_t bA0 = base + s * STG;
        uint32_t bA1 = bA0 + EST;
        uint32_t bB = bA0 + 2 * EST;
#pragma unroll
        for (int kk = 0; kk < 4; kk++) {
            uint32_t kb = kk * 32;
            uint32_t bf[4][4];  // [pp] -> {n lo k0, n lo k1, n hi k0, n hi k1}
#pragma unroll
            for (int pp = 0; pp < 4; pp++)
                LDSM4(bf[pp][0], bf[pp][1], bf[pp][2], bf[pp][3],
                      bB + bRow[pp] + (((uint32_t)colBl + kb) ^ bMask[pp]));
            uint32_t af[2][4];
#pragma unroll
            for (int ms = 0; ms < 2; ms++)
                LDSM4(af[ms][0], af[ms][1], af[ms][2], af[ms][3],
                      bA0 + aRow[ms] + (((uint32_t)colAl + kb) ^ aMask[ms]));
#pragma unroll
            for (int ms = 0; ms < 2; ms++)
#pragma unroll
                for (int pp = 0; pp < 4; pp++) {
                    mma_f16(d0[ms][2 * pp], af[ms][0], af[ms][1], af[ms][2], af[ms][3],
                            bf[pp][0], bf[pp][1]);
                    mma_f16(d0[ms][2 * pp + 1], af[ms][0], af[ms][1], af[ms][2], af[ms][3],
                            bf[pp][2], bf[pp][3]);
                }
#pragma unroll
            for (int ms = 0; ms < 2; ms++)
                LDSM4(af[ms][0], af[ms][1], af[ms][2], af[ms][3],
                      bA1 + aRow[ms] + (((uint32_t)colAl + kb) ^ aMask[ms]));
#pragma unroll
            for (int ms = 0; ms < 2; ms++)
#pragma unroll
                for (int pp = 0; pp < 4; pp++) {
                    mma_f16(d1[ms][2 * pp], af[ms][0], af[ms][1], af[ms][2], af[ms][3],
                            bf[pp][0], bf[pp][1]);
                    mma_f16(d1[ms][2 * pp + 1], af[ms][0], af[ms][1], af[ms][2], af[ms][3],
                            bf[pp][2], bf[pp][3]);
                }
        }
    }

    // Epilogue per tile: tanh + q-dot; shfl over 4 col-lanes, warps via smem
    float(*dt)[8][4] = d0;
    int tb = t0;
#pragma unroll
    for (int tile = 0; tile < 2; tile++) {
#pragma unroll
        for (int ms = 0; ms < 2; ms++) {
            float pr0 = 0.f, pr1 = 0.f;
#pragma unroll
            for (int ns = 0; ns < 8; ns++) {
                int n0 = wn * 64 + ns * 8 + 2 * laneq;
                float q0 = qs[n0], q1 = qs[n0 + 1];
                pr0 += tanhf(dt[ms][ns][0]) * q0 + tanhf(dt[ms][ns][1]) * q1;
                pr1 += tanhf(dt[ms][ns][2]) * q0 + tanhf(dt[ms][ns][3]) * q1;
            }
#pragma unroll
            for (int o = 1; o < 4; o <<= 1) {
                pr0 += __shfl_xor_sync(0xffffffffu, pr0, o);
                pr1 += __shfl_xor_sync(0xffffffffu, pr1, o);
            }
            if (laneq == 0) {
                int r = wm * 32 + ms * 16 + lane4;
                red[wn * 128 + r] = pr0;
                red[wn * 128 + r + 8] = pr1;
            }
        }
        __syncthreads();
        if (tid < 128) {
            int t = tb + tid;
            if (t < Tv)
                ebuf[(size_t)(b * Hv + h) * Tv + t] = red[tid] + red[128 + tid];
        }
        __syncthreads();
        dt = d1;
        tb = t0 + 128;
    }
}

// ---------------------------------------------------------------------------
// Masked softmax over T, in place. w = softmax(SCALING*e) on t<len, 0 else.
// ---------------------------------------------------------------------------
__global__ __launch_bounds__(256) void softmax_kernel(float* __restrict__ wbuf,
                                                      const int* __restrict__ lens) {
    int bh = blockIdx.x;
    int b = bh / Hv;
    int len = get_len(lens, b);
    int tid = threadIdx.x;
    __shared__ float s[Tv];
    __shared__ float red[16];
    float* row = wbuf + (size_t)bh * Tv;
    for (int t = tid; t < Tv; t += 256) s[t] = row[t];
    __syncthreads();

    float m = -1e30f;
    for (int t = tid; t < len; t += 256) m = fmaxf(m, s[t]);
#pragma unroll
    for (int o = 16; o; o >>= 1) m = fmaxf(m, __shfl_xor_sync(0xffffffffu, m, o));
    if ((tid & 31) == 0) red[tid >> 5] = m;
    __syncthreads();
    m = red[0];
#pragma unroll
    for (int i = 1; i < 8; i++) m = fmaxf(m, red[i]);
    float M = SCALING * m;

    float lsum = 0.f;
    for (int t = tid; t < len; t += 256) lsum += expf(SCALING * s[t] - M);
#pragma unroll
    for (int o = 16; o; o >>= 1) lsum += __shfl_xor_sync(0xffffffffu, lsum, o);
    if ((tid & 31) == 0) red[8 + (tid >> 5)] = lsum;
    __syncthreads();
    float total = 0.f;
#pragma unroll
    for (int i = 0; i < 8; i++) total += red[8 + i];
    float inv = 1.f / total;

    for (int t = tid; t < Tv; t += 256)
        row[t] = (t < len) ? expf(SCALING * s[t] - M) * inv : 0.f;
}

// ---------------------------------------------------------------------------
// u partials, vectorized (4 d per thread), unroll 4 over t for MLP.
// ---------------------------------------------------------------------------
__global__ __launch_bounds__(256) void u_kernel(const float* __restrict__ wbuf,
                                                const int* __restrict__ lens) {
    int tc = blockIdx.x, b = blockIdx.y;
    int d0 = threadIdx.x * 4;
    int len = get_len(lens, b);
    int t0 = tc * 128;
    float* up = g_up + (((size_t)tc * Bv + b) * Hv) * Ev + d0;
    if (t0 >= len) {
#pragma unroll
        for (int h = 0; h < Hv; h++)
            *(float4*)(up + (size_t)h * Ev) = make_float4(0.f, 0.f, 0.f, 0.f);
        return;
    }
    int tmax = min(min(128, Tv - t0), len - t0);
    __shared__ float ws[Hv][128];
#pragma unroll
    for (int r = 0; r < 4; r++) {
        int f = r * 256 + threadIdx.x;
        int h = f >> 7, tt = f & 127;
        int t = t0 + tt;
        ws[h][tt] = (t < Tv) ? wbuf[((size_t)(b * Hv + h)) * Tv + t] : 0.f;
    }
    __syncthreads();

    float acc[Hv][4];
#pragma unroll
    for (int h = 0; h < Hv; h++)
#pragma unroll
        for (int j = 0; j < 4; j++) acc[h][j] = 0.f;

    const __half* A = g_enc16 + (size_t)b * Tv * Ev + (size_t)t0 * Ev + d0;
#pragma unroll 4
    for (int tt = 0; tt < tmax; tt++) {
        uint2 raw = *(const uint2*)(A + (size_t)tt * Ev);
        float2 x01 = __half22float2(*(__half2*)&raw.x);
        float2 x23 = __half22float2(*(__half2*)&raw.y);
#pragma unroll
        for (int h = 0; h < Hv; h++) {
            float w = ws[h][tt];
            acc[h][0] += w * x01.x;
            acc[h][1] += w * x01.y;
            acc[h][2] += w * x23.x;
            acc[h][3] += w * x23.y;
        }
    }
#pragma unroll
    for (int h = 0; h < Hv; h++)
        *(float4*)(up + (size_t)h * Ev) =
            make_float4(acc[h][0], acc[h][1], acc[h][2], acc[h][3]);
}

// ---------------------------------------------------------------------------
// c[b,h,v] = u[b,h,:]·Wv[h,:,v]; 4 accumulators for MLP.
// ---------------------------------------------------------------------------
__global__ __launch_bounds__(128) void c_kernel(const float* __restrict__ Wv) {
    int h = blockIdx.x, b = blockIdx.y;
    int v = threadIdx.x;
    __shared__ float us[Ev];
    for (int i = v; i < Ev; i += 128) {
        float s0 = 0.f, s1 = 0.f;
#pragma unroll
        for (int tc = 0; tc < TCHUNK; tc += 2) {
            s0 += g_up[(((size_t)tc * Bv + b) * Hv + h) * Ev + i];
            s1 += g_up[(((size_t)(tc + 1) * Bv + b) * Hv + h) * Ev + i];
        }
        us[i] = s0 + s1;
    }
    __syncthreads();
    const float* W = Wv + (size_t)h * Ev * DVv + v;
    float a[4] = {0.f, 0.f, 0.f, 0.f};
#pragma unroll 4
    for (int d = 0; d < Ev; d += 4) {
        a[0] += us[d] * W[(size_t)d * DVv];
        a[1] += us[d + 1] * W[(size_t)(d + 1) * DVv];
        a[2] += us[d + 2] * W[(size_t)(d + 2) * DVv];
        a[3] += us[d + 3] * W[(size_t)(d + 3) * DVv];
    }
    g_c[(b * Hv + h) * DVv + v] = (a[0] + a[1]) + (a[2] + a[3]);
}

// ---------------------------------------------------------------------------
// out[b,e] = c_flat[b,:]·Wo[:,e]; 4 accumulators for MLP.
// ---------------------------------------------------------------------------
__global__ __launch_bounds__(256) void out_kernel(const float* __restrict__ Wo,
                                                  float* __restrict__ out) {
    int chunk = blockIdx.x, b = blockIdx.y;
    int e = chunk * 256 + threadIdx.x;
    __shared__ float cs[Hv * DVv];
    for (int i = threadIdx.x; i < Hv * DVv; i += 256) cs[i] = g_c[b * Hv * DVv + i];
    __syncthreads();
    float a[4] = {0.f, 0.f, 0.f, 0.f};
#pragma unroll 4
    for (int i = 0; i < Hv * DVv; i += 4) {
        a[0] += cs[i] * Wo[(size_t)i * Ev + e];
        a[1] += cs[i + 1] * Wo[(size_t)(i + 1) * Ev + e];
        a[2] += cs[i + 2] * Wo[(size_t)(i + 2) * Ev + e];
        a[3] += cs[i + 3] * Wo[(size_t)(i + 3) * Ev + e];
    }
    out[(size_t)b * Ev + e] = (a[0] + a[1]) + (a[2] + a[3]);
}

// ---------------------------------------------------------------------------
extern "C" void kernel_launch(void* const* d_in, const int* in_sizes, int n_in,
                              void* d_out, int out_size) {
    const float* enc   = (const float*)d_in[0];
    const int*   lens  = (const int*)d_in[1];
    const float* dec_z = (const float*)d_in[2];
    const float* Wq    = (const float*)d_in[3];
    const float* bq    = (const float*)d_in[4];
    const float* Wk    = (const float*)d_in[5];
    const float* Wv    = (const float*)d_in[6];
    const float* Wo    = (const float*)d_in[7];

    float* out  = (float*)d_out;   // (B,E)
    float* wbuf = out + Bv * Ev;   // (B,H,T): e logits, then w in place

    static int smem_set = 0;
    if (!smem_set) {
        cudaFuncSetAttribute(e_tc_kernel, cudaFuncAttributeMaxDynamicSharedMemorySize, E_SMEM);
        smem_set = 1;
    }

    enc16_kernel<<<(Bv * Tv * Ev) / (256 * 8), 256>>>(enc, lens);
    wkT16_kernel<<<dim3(Ev / 32, DKv / 32, Hv), 256>>>(Wk);
    q_kernel<<<dim3(Hv, Bv), 128>>>(dec_z, Wq, bq);
    e_tc_kernel<<<dim3(Hv, (Tv + 255) / 256, Bv), 256, E_SMEM>>>(wbuf, lens);
    softmax_kernel<<<Bv * Hv, 256>>>(wbuf, lens);
    u_kernel<<<dim3(TCHUNK, Bv), 256>>>(wbuf, lens);
    c_kernel<<<dim3(Hv, Bv), 128>>>(Wv);
    out_kernel<<<dim3(Ev / 256, Bv), 256>>>(Wo, out);
}

// round 11
// speedup vs baseline: 1.0948x; 1.0948x over previous
#include <cuda_runtime.h>
#include <cuda_fp16.h>
#include <cstdint>

#define Bv 32
#define Tv 1500
#define Ev 1024
#define Hv 8
#define DKv 128
#define DVv 128
#define Dv 1024
#define SCALING 0.088388347648318447f  // 1/sqrt(128)
#define TCHUNK 12

// Scratch (no allocations allowed)
__device__ float g_q[Bv * Hv * DKv];            // tanh(dec_z@Wq + bq)
__device__ float g_c[Bv * Hv * DVv];            // u @ Wv
__device__ float g_up[TCHUNK * Bv * Hv * Ev];   // u partials over t-chunks
__device__ __half g_enc16[(size_t)Bv * Tv * Ev];   // enc in fp16 (98.3 MB)
__device__ __half g_wkT16[(size_t)Hv * DKv * Ev];  // Wk^T in fp16: [h][n][e]

// ---------------------------------------------------------------------------
// PTX helpers (sm_80-level only; tcgen05 is rejected by this harness target)
// ---------------------------------------------------------------------------
__device__ __forceinline__ uint32_t smem_u32(const void* p) {
    uint32_t a;
    asm("{ .reg .u64 t; cvta.to.shared.u64 t, %1; cvt.u32.u64 %0, t; }" : "=r"(a) : "l"(p));
    return a;
}
#define CP16(sm, gm, sz) \
    asm volatile("cp.async.cg.shared.global [%0], [%1], 16, %2;" ::"r"(sm), "l"(gm), "r"(sz) : "memory")
#define CP_COMMIT() asm volatile("cp.async.commit_group;" ::: "memory")
#define CP_WAIT1() asm volatile("cp.async.wait_group 1;" ::: "memory")
#define LDSM4(r0, r1, r2, r3, a)                                             \
    asm volatile("ldmatrix.sync.aligned.m8n8.x4.shared.b16 {%0,%1,%2,%3}, [%4];" \
                 : "=r"(r0), "=r"(r1), "=r"(r2), "=r"(r3) : "r"(a))

__device__ __forceinline__ void mma_f16(float* d, uint32_t a0, uint32_t a1, uint32_t a2,
                                        uint32_t a3, uint32_t b0, uint32_t b1) {
    asm volatile(
        "mma.sync.aligned.m16n8k16.row.col.f32.f16.f16.f32 "
        "{%0,%1,%2,%3}, {%4,%5,%6,%7}, {%8,%9}, {%0,%1,%2,%3};"
        : "+f"(d[0]), "+f"(d[1]), "+f"(d[2]), "+f"(d[3])
        : "r"(a0), "r"(a1), "r"(a2), "r"(a3), "r"(b0), "r"(b1));
}
__device__ __forceinline__ uint32_t sw128(uint32_t o) { return o ^ ((o >> 3) & 0x70); }

// ---------------------------------------------------------------------------
// Length read with dtype sniff (int64 declared, int32 in practice)
// ---------------------------------------------------------------------------
__device__ __forceinline__ int get_len(const int* __restrict__ L, int b) {
    bool is64 = (L[1] == 0);
    return is64 ? L[2 * b] : L[b];
}

// ---------------------------------------------------------------------------
// enc -> fp16 (round-to-nearest), clipped to ceil128(len) rows per batch.
// ---------------------------------------------------------------------------
__global__ __launch_bounds__(256) void enc16_kernel(const float* __restrict__ enc,
                                                    const int* __restrict__ lens) {
    size_t base = ((size_t)blockIdx.x * 256 + threadIdx.x) * 8;
    int t = (int)((base / Ev) % Tv);
    int b = (int)(base / ((size_t)Ev * Tv));
    int len = get_len(lens, b);
    if (t >= ((len + 127) & ~127)) return;
    float4 v0 = *(const float4*)(enc + base);
    float4 v1 = *(const float4*)(enc + base + 4);
    __half2 h[4];
    h[0] = __floats2half2_rn(v0.x, v0.y);
    h[1] = __floats2half2_rn(v0.z, v0.w);
    h[2] = __floats2half2_rn(v1.x, v1.y);
    h[3] = __floats2half2_rn(v1.z, v1.w);
    *(uint4*)(g_enc16 + base) = *(uint4*)h;
}

// ---------------------------------------------------------------------------
// wkT16[h][n][e] = fp16(Wk[h][e][n])
// ---------------------------------------------------------------------------
__global__ __launch_bounds__(256) void wkT16_kernel(const float* __restrict__ Wk) {
    __shared__ float tile[32][33];
    int e0 = blockIdx.x * 32, n0 = blockIdx.y * 32, h = blockIdx.z;
    int tx = threadIdx.x & 31, ty = threadIdx.x >> 5;
    for (int i = ty; i < 32; i += 8)
        tile[i][tx] = Wk[((size_t)h * Ev + e0 + i) * DKv + n0 + tx];
    __syncthreads();
    for (int i = ty; i < 32; i += 8)
        g_wkT16[((size_t)h * DKv + n0 + i) * Ev + e0 + tx] = __float2half_rn(tile[tx][i]);
}

// ---------------------------------------------------------------------------
// q[b,h,k] = tanh(dec_z[b,:]·Wq[h,:,k] + bq[h,k]); 4 accumulators for MLP.
// ---------------------------------------------------------------------------
__global__ __launch_bounds__(128) void q_kernel(const float* __restrict__ dec_z,
                                                const float* __restrict__ Wq,
                                                const float* __restrict__ bq) {
    int h = blockIdx.x, b = blockIdx.y;
    int k = threadIdx.x;
    __shared__ float zs[Dv];
    for (int i = k; i < Dv; i += 128) zs[i] = dec_z[b * Dv + i];
    __syncthreads();
    const float* W = Wq + (size_t)h * Dv * DKv + k;
    float a[4] = {0.f, 0.f, 0.f, 0.f};
#pragma unroll 4
    for (int d = 0; d < Dv; d += 4) {
        a[0] += zs[d] * W[(size_t)d * DKv];
        a[1] += zs[d + 1] * W[(size_t)(d + 1) * DKv];
        a[2] += zs[d + 2] * W[(size_t)(d + 2) * DKv];
        a[3] += zs[d + 3] * W[(size_t)(d + 3) * DKv];
    }
    g_q[(b * Hv + h) * DKv + k] = tanhf(bq[h * DKv + k] + (a[0] + a[1]) + (a[2] + a[3]));
}

// ---------------------------------------------------------------------------
// e[b,h,t] = sum_n tanh( (enc@Wk[h])[t,n] ) * q[b,h,n]
// fp16 m16n8k16 GEMM (R9 config: 128-t tile, 2 CTA/SM, 128 regs).
// 3-stage cp.async ring, precomputed swizzled addrs, ldmatrix.x4 fragments.
// ---------------------------------------------------------------------------
#define ECH 64                 // K halves per stage (128 B per row)
#define ENCH (Ev / ECH)        // 16 chunks
#define EST 16384              // one tile stage: 128 rows * 128 B
#define NSTG 3
#define OFF_QS (2 * NSTG * EST)          // 98304
#define OFF_RED (OFF_QS + 512)
#define E_SMEM (OFF_RED + 1024)          // 99840 (x2 CTAs fits 228KB)

__global__ __launch_bounds__(256, 2) void e_tc_kernel(float* __restrict__ ebuf,
                                                      const int* __restrict__ lens) {
    extern __shared__ __align__(16) char dsm[];
    float* qs = (float*)(dsm + OFF_QS);
    float* red = (float*)(dsm + OFF_RED);  // [2][128]

    int tid = threadIdx.x, wid = tid >> 5, lane = tid & 31;
    int h = blockIdx.x, tile = blockIdx.y, b = blockIdx.z;
    int t0 = tile * 128;
    int len = get_len(lens, b);
    if (t0 >= len) return;  // dead tile: softmax writes 0 over this range

    int wm = wid & 3, wn = wid >> 2;
    int lane4 = lane >> 2, laneq = lane & 3;

    if (tid < DKv) qs[tid] = g_q[(b * Hv + h) * DKv + tid];

    const __half* A = g_enc16 + (size_t)b * Tv * Ev;
    const __half* Wt = g_wkT16 + (size_t)h * DKv * Ev;

    uint32_t base = smem_u32(dsm);

    uint32_t swz[4];
    const __half* pA[4];
    const __half* pB[4];
    uint32_t szA[4];
#pragma unroll
    for (int r = 0; r < 4; r++) {
        int idx = r * 256 + tid;
        int row = idx >> 3, seg = idx & 7;
        swz[r] = sw128(row * 128 + seg * 16);
        int t = t0 + row;
        szA[r] = (t < Tv) ? 16u : 0u;
        pA[r] = A + (size_t)t * Ev + seg * 8;
        pB[r] = Wt + (size_t)row * Ev + seg * 8;
    }

    auto issue = [&](int c, int s) {
        int k0 = c * ECH;
        uint32_t bA = base + s * EST, bB = base + (NSTG + s) * EST;
#pragma unroll
        for (int r = 0; r < 4; r++) CP16(bA + swz[r], pA[r] + k0, szA[r]);
#pragma unroll
        for (int r = 0; r < 4; r++) CP16(bB + swz[r], pB[r] + k0, 16u);
        CP_COMMIT();
    };

    int rowAl = (lane & 7) + ((lane >> 3) & 1) * 8;
    int colAl = ((lane >> 4) & 1) * 16;
    int rowBl = (lane & 7) + ((lane >> 4) & 1) * 8;
    int colBl = ((lane >> 3) & 1) * 16;
    uint32_t aRow[2], aMask[2];
#pragma unroll
    for (int ms = 0; ms < 2; ms++) {
        int row = wm * 32 + ms * 16 + rowAl;
        aRow[ms] = row * 128;
        aMask[ms] = (row & 7) << 4;
    }
    uint32_t bRow[4], bMask[4];
#pragma unroll
    for (int pp = 0; pp < 4; pp++) {
        int row = wn * 64 + pp * 16 + rowBl;
        bRow[pp] = row * 128;
        bMask[pp] = (row & 7) << 4;
    }

    float d[2][8][4];
#pragma unroll
    for (int ms = 0; ms < 2; ms++)
#pragma unroll
        for (int ns = 0; ns < 8; ns++)
#pragma unroll
            for (int j = 0; j < 4; j++) d[ms][ns][j] = 0.f;

    issue(0, 0);
    issue(1, 1);

    for (int c = 0; c < ENCH; c++) {
        int s = c % NSTG;
        CP_WAIT1();
        __syncthreads();
        if (c + 2 < ENCH) issue(c + 2, (c + 2) % NSTG);
        uint32_t bA = base + s * EST, bB = base + (NSTG + s) * EST;
#pragma unroll
        for (int kk = 0; kk < 4; kk++) {
            uint32_t kb = kk * 32;
            uint32_t af[2][4];
#pragma unroll
            for (int ms = 0; ms < 2; ms++)
                LDSM4(af[ms][0], af[ms][1], af[ms][2], af[ms][3],
                      bA + aRow[ms] + (((uint32_t)colAl + kb) ^ aMask[ms]));
            uint32_t bf[8][2];
#pragma unroll
            for (int pp = 0; pp < 4; pp++)
                LDSM4(bf[2 * pp][0], bf[2 * pp][1], bf[2 * pp + 1][0], bf[2 * pp + 1][1],
                      bB + bRow[pp] + (((uint32_t)colBl + kb) ^ bMask[pp]));
#pragma unroll
            for (int ms = 0; ms < 2; ms++)
#pragma unroll
                for (int ns = 0; ns < 8; ns++)
                    mma_f16(d[ms][ns], af[ms][0], af[ms][1], af[ms][2], af[ms][3],
                            bf[ns][0], bf[ns][1]);
        }
    }

    // Epilogue: tanh + q-dot; reduce over cols (4 lanes) via shfl, warps via smem
#pragma unroll
    for (int ms = 0; ms < 2; ms++) {
        float pr0 = 0.f, pr1 = 0.f;
#pragma unroll
        for (int ns = 0; ns < 8; ns++) {
            int n0 = wn * 64 + ns * 8 + 2 * laneq;
            float q0 = qs[n0], q1 = qs[n0 + 1];
            pr0 += tanhf(d[ms][ns][0]) * q0 + tanhf(d[ms][ns][1]) * q1;
            pr1 += tanhf(d[ms][ns][2]) * q0 + tanhf(d[ms][ns][3]) * q1;
        }
#pragma unroll
        for (int o = 1; o < 4; o <<= 1) {
            pr0 += __shfl_xor_sync(0xffffffffu, pr0, o);
            pr1 += __shfl_xor_sync(0xffffffffu, pr1, o);
        }
        if (laneq == 0) {
            int r = wm * 32 + ms * 16 + lane4;
            red[wn * 128 + r] = pr0;
            red[wn * 128 + r + 8] = pr1;
        }
    }
    __syncthreads();
    if (tid < 128) {
        int t = t0 + tid;
        if (t < Tv)
            ebuf[(size_t)(b * Hv + h) * Tv + t] = red[tid] + red[128 + tid];
    }
}

// ---------------------------------------------------------------------------
// Masked softmax over T, in place. w = softmax(SCALING*e) on t<len, 0 else.
// ---------------------------------------------------------------------------
__global__ __launch_bounds__(256) void softmax_kernel(float* __restrict__ wbuf,
                                                      const int* __restrict__ lens) {
    int bh = blockIdx.x;
    int b = bh / Hv;
    int len = get_len(lens, b);
    int tid = threadIdx.x;
    __shared__ float s[Tv];
    __shared__ float red[16];
    float* row = wbuf + (size_t)bh * Tv;
    for (int t = tid; t < Tv; t += 256) s[t] = row[t];
    __syncthreads();

    float m = -1e30f;
    for (int t = tid; t < len; t += 256) m = fmaxf(m, s[t]);
#pragma unroll
    for (int o = 16; o; o >>= 1) m = fmaxf(m, __shfl_xor_sync(0xffffffffu, m, o));
    if ((tid & 31) == 0) red[tid >> 5] = m;
    __syncthreads();
    m = red[0];
#pragma unroll
    for (int i = 1; i < 8; i++) m = fmaxf(m, red[i]);
    float M = SCALING * m;

    float lsum = 0.f;
    for (int t = tid; t < len; t += 256) lsum += expf(SCALING * s[t] - M);
#pragma unroll
    for (int o = 16; o; o >>= 1) lsum += __shfl_xor_sync(0xffffffffu, lsum, o);
    if ((tid & 31) == 0) red[8 + (tid >> 5)] = lsum;
    __syncthreads();
    float total = 0.f;
#pragma unroll
    for (int i = 0; i < 8; i++) total += red[8 + i];
    float inv = 1.f / total;

    for (int t = tid; t < Tv; t += 256)
        row[t] = (t < len) ? expf(SCALING * s[t] - M) * inv : 0.f;
}

// ---------------------------------------------------------------------------
// u partials, vectorized (4 d per thread), unroll 4 over t for MLP.
// ---------------------------------------------------------------------------
__global__ __launch_bounds__(256) void u_kernel(const float* __restrict__ wbuf,
                                                const int* __restrict__ lens) {
    int tc = blockIdx.x, b = blockIdx.y;
    int d0 = threadIdx.x * 4;
    int len = get_len(lens, b);
    int t0 = tc * 128;
    float* up = g_up + (((size_t)tc * Bv + b) * Hv) * Ev + d0;
    if (t0 >= len) {
#pragma unroll
        for (int h = 0; h < Hv; h++)
            *(float4*)(up + (size_t)h * Ev) = make_float4(0.f, 0.f, 0.f, 0.f);
        return;
    }
    int tmax = min(min(128, Tv - t0), len - t0);
    __shared__ float ws[Hv][128];
#pragma unroll
    for (int r = 0; r < 4; r++) {
        int f = r * 256 + threadIdx.x;
        int h = f >> 7, tt = f & 127;
        int t = t0 + tt;
        ws[h][tt] = (t < Tv) ? wbuf[((size_t)(b * Hv + h)) * Tv + t] : 0.f;
    }
    __syncthreads();

    float acc[Hv][4];
#pragma unroll
    for (int h = 0; h < Hv; h++)
#pragma unroll
        for (int j = 0; j < 4; j++) acc[h][j] = 0.f;

    const __half* A = g_enc16 + (size_t)b * Tv * Ev + (size_t)t0 * Ev + d0;
#pragma unroll 4
    for (int tt = 0; tt < tmax; tt++) {
        uint2 raw = *(const uint2*)(A + (size_t)tt * Ev);
        float2 x01 = __half22float2(*(__half2*)&raw.x);
        float2 x23 = __half22float2(*(__half2*)&raw.y);
#pragma unroll
        for (int h = 0; h < Hv; h++) {
            float w = ws[h][tt];
            acc[h][0] += w * x01.x;
            acc[h][1] += w * x01.y;
            acc[h][2] += w * x23.x;
            acc[h][3] += w * x23.y;
        }
    }
#pragma unroll
    for (int h = 0; h < Hv; h++)
        *(float4*)(up + (size_t)h * Ev) =
            make_float4(acc[h][0], acc[h][1], acc[h][2], acc[h][3]);
}

// ---------------------------------------------------------------------------
// c[b,h,v] = u[b,h,:]·Wv[h,:,v]; 4 accumulators for MLP.
// ---------------------------------------------------------------------------
__global__ __launch_bounds__(128) void c_kernel(const float* __restrict__ Wv) {
    int h = blockIdx.x, b = blockIdx.y;
    int v = threadIdx.x;
    __shared__ float us[Ev];
    for (int i = v; i < Ev; i += 128) {
        float s0 = 0.f, s1 = 0.f;
#pragma unroll
        for (int tc = 0; tc < TCHUNK; tc += 2) {
            s0 += g_up[(((size_t)tc * Bv + b) * Hv + h) * Ev + i];
            s1 += g_up[(((size_t)(tc + 1) * Bv + b) * Hv + h) * Ev + i];
        }
        us[i] = s0 + s1;
    }
    __syncthreads();
    const float* W = Wv + (size_t)h * Ev * DVv + v;
    float a[4] = {0.f, 0.f, 0.f, 0.f};
#pragma unroll 4
    for (int d = 0; d < Ev; d += 4) {
        a[0] += us[d] * W[(size_t)d * DVv];
        a[1] += us[d + 1] * W[(size_t)(d + 1) * DVv];
        a[2] += us[d + 2] * W[(size_t)(d + 2) * DVv];
        a[3] += us[d + 3] * W[(size_t)(d + 3) * DVv];
    }
    g_c[(b * Hv + h) * DVv + v] = (a[0] + a[1]) + (a[2] + a[3]);
}

// ---------------------------------------------------------------------------
// out[b,e] = c_flat[b,:]·Wo[:,e]; 4 accumulators for MLP.
// ---------------------------------------------------------------------------
__global__ __launch_bounds__(256) void out_kernel(const float* __restrict__ Wo,
                                                  float* __restrict__ out) {
    int chunk = blockIdx.x, b = blockIdx.y;
    int e = chunk * 256 + threadIdx.x;
    __shared__ float cs[Hv * DVv];
    for (int i = threadIdx.x; i < Hv * DVv; i += 256) cs[i] = g_c[b * Hv * DVv + i];
    __syncthreads();
    float a[4] = {0.f, 0.f, 0.f, 0.f};
#pragma unroll 4
    for (int i = 0; i < Hv * DVv; i += 4) {
        a[0] += cs[i] * Wo[(size_t)i * Ev + e];
        a[1] += cs[i + 1] * Wo[(size_t)(i + 1) * Ev + e];
        a[2] += cs[i + 2] * Wo[(size_t)(i + 2) * Ev + e];
        a[3] += cs[i + 3] * Wo[(size_t)(i + 3) * Ev + e];
    }
    out[(size_t)b * Ev + e] = (a[0] + a[1]) + (a[2] + a[3]);
}

// ---------------------------------------------------------------------------
extern "C" void kernel_launch(void* const* d_in, const int* in_sizes, int n_in,
                              void* d_out, int out_size) {
    const float* enc   = (const float*)d_in[0];
    const int*   lens  = (const int*)d_in[1];
    const float* dec_z = (const float*)d_in[2];
    const float* Wq    = (const float*)d_in[3];
    const float* bq    = (const float*)d_in[4];
    const float* Wk    = (const float*)d_in[5];
    const float* Wv    = (const float*)d_in[6];
    const float* Wo    = (const float*)d_in[7];

    float* out  = (float*)d_out;   // (B,E)
    float* wbuf = out + Bv * Ev;   // (B,H,T): e logits, then w in place

    static cudaStream_t s2 = nullptr, s3 = nullptr;
    static cudaEvent_t evFork = nullptr, evJ2 = nullptr, evJ3 = nullptr;
    static int inited = 0;
    if (!inited) {
        cudaFuncSetAttribute(e_tc_kernel, cudaFuncAttributeMaxDynamicSharedMemorySize, E_SMEM);
        cudaStreamCreateWithFlags(&s2, cudaStreamNonBlocking);
        cudaStreamCreateWithFlags(&s3, cudaStreamNonBlocking);
        cudaEventCreateWithFlags(&evFork, cudaEventDisableTiming);
        cudaEventCreateWithFlags(&evJ2, cudaEventDisableTiming);
        cudaEventCreateWithFlags(&evJ3, cudaEventDisableTiming);
        inited = 1;
    }

    // Fork: enc16 on main stream; wkT16 and q on side streams (independent).
    cudaEventRecord(evFork, 0);
    cudaStreamWaitEvent(s2, evFork, 0);
    cudaStreamWaitEvent(s3, evFork, 0);

    enc16_kernel<<<(Bv * Tv * Ev) / (256 * 8), 256>>>(enc, lens);
    wkT16_kernel<<<dim3(Ev / 32, DKv / 32, Hv), 256, 0, s2>>>(Wk);
    q_kernel<<<dim3(Hv, Bv), 128, 0, s3>>>(dec_z, Wq, bq);

    // Join: e_tc needs enc16 + wkT16 + q.
    cudaEventRecord(evJ2, s2);
    cudaEventRecord(evJ3, s3);
    cudaStreamWaitEvent(0, evJ2, 0);
    cudaStreamWaitEvent(0, evJ3, 0);

    e_tc_kernel<<<dim3(Hv, (Tv + 127) / 128, Bv), 256, E_SMEM>>>(wbuf, lens);
    softmax_kernel<<<Bv * Hv, 256>>>(wbuf, lens);
    u_kernel<<<dim3(TCHUNK, Bv), 256>>>(wbuf, lens);
    c_kernel<<<dim3(Hv, Bv), 128>>>(Wv);
    out_kernel<<<dim3(Ev / 256, Bv), 256>>>(Wo, out);
}

// round 12
// speedup vs baseline: 1.1527x; 1.0529x over previous
#include <cuda_runtime.h>
#include <cuda_fp16.h>
#include <cstdint>

#define Bv 32
#define Tv 1500
#define Ev 1024
#define Hv 8
#define DKv 128
#define DVv 128
#define Dv 1024
#define SCALING 0.088388347648318447f  // 1/sqrt(128)
#define TCHUNK 12

// Scratch (no allocations allowed)
__device__ float g_q[Bv * Hv * DKv];            // tanh(dec_z@Wq + bq)
__device__ float g_c[Bv * Hv * DVv];            // u @ Wv
__device__ float g_up[TCHUNK * Bv * Hv * Ev];   // u partials over t-chunks
__device__ __half g_enc16[(size_t)Bv * Tv * Ev];   // enc in fp16 (98.3 MB)
__device__ __half g_wkT16[(size_t)Hv * DKv * Ev];  // Wk^T in fp16: [h][n][e]

// ---------------------------------------------------------------------------
// PTX helpers (sm_80-level only; tcgen05 is rejected by this harness target)
// ---------------------------------------------------------------------------
__device__ __forceinline__ uint32_t smem_u32(const void* p) {
    uint32_t a;
    asm("{ .reg .u64 t; cvta.to.shared.u64 t, %1; cvt.u32.u64 %0, t; }" : "=r"(a) : "l"(p));
    return a;
}
#define CP16(sm, gm, sz) \
    asm volatile("cp.async.cg.shared.global [%0], [%1], 16, %2;" ::"r"(sm), "l"(gm), "r"(sz) : "memory")
#define CP_COMMIT() asm volatile("cp.async.commit_group;" ::: "memory")
#define CP_WAIT1() asm volatile("cp.async.wait_group 1;" ::: "memory")
#define LDSM4(r0, r1, r2, r3, a)                                             \
    asm volatile("ldmatrix.sync.aligned.m8n8.x4.shared.b16 {%0,%1,%2,%3}, [%4];" \
                 : "=r"(r0), "=r"(r1), "=r"(r2), "=r"(r3) : "r"(a))

__device__ __forceinline__ void mma_f16(float* d, uint32_t a0, uint32_t a1, uint32_t a2,
                                        uint32_t a3, uint32_t b0, uint32_t b1) {
    asm volatile(
        "mma.sync.aligned.m16n8k16.row.col.f32.f16.f16.f32 "
        "{%0,%1,%2,%3}, {%4,%5,%6,%7}, {%8,%9}, {%0,%1,%2,%3};"
        : "+f"(d[0]), "+f"(d[1]), "+f"(d[2]), "+f"(d[3])
        : "r"(a0), "r"(a1), "r"(a2), "r"(a3), "r"(b0), "r"(b1));
}
__device__ __forceinline__ uint32_t sw128(uint32_t o) { return o ^ ((o >> 3) & 0x70); }

// ---------------------------------------------------------------------------
// Length read with dtype sniff (int64 declared, int32 in practice)
// ---------------------------------------------------------------------------
__device__ __forceinline__ int get_len(const int* __restrict__ L, int b) {
    bool is64 = (L[1] == 0);
    return is64 ? L[2 * b] : L[b];
}

// ---------------------------------------------------------------------------
// Fused prep: enc->fp16 (clipped), WkT fp16 transpose, q projection.
// Independent sub-tasks dispatched by block range; they jointly gate e_tc.
// ---------------------------------------------------------------------------
#define ENCB ((Bv * Tv * Ev) / (256 * 8))   // 24000
#define WKTB ((Ev / 32) * (DKv / 32) * Hv)  // 1024
#define QB ((Hv / 2) * Bv)                  // 128
#define PREPB (ENCB + WKTB + QB)

__global__ __launch_bounds__(256) void prep_kernel(const float* __restrict__ enc,
                                                   const int* __restrict__ lens,
                                                   const float* __restrict__ Wk,
                                                   const float* __restrict__ dec_z,
                                                   const float* __restrict__ Wq,
                                                   const float* __restrict__ bq) {
    int bx = blockIdx.x;
    if (bx < ENCB) {
        // ---- enc -> fp16, clipped to ceil128(len) rows per batch ----
        size_t base = ((size_t)bx * 256 + threadIdx.x) * 8;
        int t = (int)((base / Ev) % Tv);
        int b = (int)(base / ((size_t)Ev * Tv));
        int len = get_len(lens, b);
        if (t >= ((len + 127) & ~127)) return;
        float4 v0 = *(const float4*)(enc + base);
        float4 v1 = *(const float4*)(enc + base + 4);
        __half2 h[4];
        h[0] = __floats2half2_rn(v0.x, v0.y);
        h[1] = __floats2half2_rn(v0.z, v0.w);
        h[2] = __floats2half2_rn(v1.x, v1.y);
        h[3] = __floats2half2_rn(v1.z, v1.w);
        *(uint4*)(g_enc16 + base) = *(uint4*)h;
    } else if (bx < ENCB + WKTB) {
        // ---- wkT16[h][n][e] = fp16(Wk[h][e][n]) ----
        __shared__ float tile[32][33];
        int idx = bx - ENCB;
        int e0 = (idx & 31) * 32;          // Ev/32 = 32
        int n0 = ((idx >> 5) & 3) * 32;    // DKv/32 = 4
        int h = idx >> 7;                  // Hv = 8
        int tx = threadIdx.x & 31, ty = threadIdx.x >> 5;
        for (int i = ty; i < 32; i += 8)
            tile[i][tx] = Wk[((size_t)h * Ev + e0 + i) * DKv + n0 + tx];
        __syncthreads();
        for (int i = ty; i < 32; i += 8)
            g_wkT16[((size_t)h * DKv + n0 + i) * Ev + e0 + tx] = __float2half_rn(tile[tx][i]);
    } else {
        // ---- q[b,h,k] = tanh(dec_z[b]·Wq[h,:,k] + bq[h,k]); 2 heads/block ----
        __shared__ float zs[Dv];
        int idx = bx - ENCB - WKTB;        // 0..127
        int b = idx >> 2;
        int h = (idx & 3) * 2 + (threadIdx.x >> 7);
        int k = threadIdx.x & 127;
        for (int i = threadIdx.x; i < Dv; i += 256) zs[i] = dec_z[b * Dv + i];
        __syncthreads();
        const float* W = Wq + (size_t)h * Dv * DKv + k;
        float a[4] = {0.f, 0.f, 0.f, 0.f};
#pragma unroll 4
        for (int d = 0; d < Dv; d += 4) {
            a[0] += zs[d] * W[(size_t)d * DKv];
            a[1] += zs[d + 1] * W[(size_t)(d + 1) * DKv];
            a[2] += zs[d + 2] * W[(size_t)(d + 2) * DKv];
            a[3] += zs[d + 3] * W[(size_t)(d + 3) * DKv];
        }
        g_q[(b * Hv + h) * DKv + k] =
            tanhf(bq[h * DKv + k] + (a[0] + a[1]) + (a[2] + a[3]));
    }
}

// ---------------------------------------------------------------------------
// e[b,h,t] = sum_n tanh( (enc@Wk[h])[t,n] ) * q[b,h,n]
// fp16 m16n8k16 GEMM (R9 config: 128-t tile, 2 CTA/SM, 128 regs).
// 3-stage cp.async ring, precomputed swizzled addrs, ldmatrix.x4 fragments.
// ---------------------------------------------------------------------------
#define ECH 64                 // K halves per stage (128 B per row)
#define ENCH (Ev / ECH)        // 16 chunks
#define EST 16384              // one tile stage: 128 rows * 128 B
#define NSTG 3
#define OFF_QS (2 * NSTG * EST)          // 98304
#define OFF_RED (OFF_QS + 512)
#define E_SMEM (OFF_RED + 1024)          // 99840 (x2 CTAs fits 228KB)

__global__ __launch_bounds__(256, 2) void e_tc_kernel(float* __restrict__ ebuf,
                                                      const int* __restrict__ lens) {
    extern __shared__ __align__(16) char dsm[];
    float* qs = (float*)(dsm + OFF_QS);
    float* red = (float*)(dsm + OFF_RED);  // [2][128]

    int tid = threadIdx.x, wid = tid >> 5, lane = tid & 31;
    int h = blockIdx.x, tile = blockIdx.y, b = blockIdx.z;
    int t0 = tile * 128;
    int len = get_len(lens, b);
    if (t0 >= len) return;  // dead tile: softmax writes 0 over this range

    int wm = wid & 3, wn = wid >> 2;
    int lane4 = lane >> 2, laneq = lane & 3;

    if (tid < DKv) qs[tid] = g_q[(b * Hv + h) * DKv + tid];

    const __half* A = g_enc16 + (size_t)b * Tv * Ev;
    const __half* Wt = g_wkT16 + (size_t)h * DKv * Ev;

    uint32_t base = smem_u32(dsm);

    uint32_t swz[4];
    const __half* pA[4];
    const __half* pB[4];
    uint32_t szA[4];
#pragma unroll
    for (int r = 0; r < 4; r++) {
        int idx = r * 256 + tid;
        int row = idx >> 3, seg = idx & 7;
        swz[r] = sw128(row * 128 + seg * 16);
        int t = t0 + row;
        szA[r] = (t < Tv) ? 16u : 0u;
        pA[r] = A + (size_t)t * Ev + seg * 8;
        pB[r] = Wt + (size_t)row * Ev + seg * 8;
    }

    auto issue = [&](int c, int s) {
        int k0 = c * ECH;
        uint32_t bA = base + s * EST, bB = base + (NSTG + s) * EST;
#pragma unroll
        for (int r = 0; r < 4; r++) CP16(bA + swz[r], pA[r] + k0, szA[r]);
#pragma unroll
        for (int r = 0; r < 4; r++) CP16(bB + swz[r], pB[r] + k0, 16u);
        CP_COMMIT();
    };

    int rowAl = (lane & 7) + ((lane >> 3) & 1) * 8;
    int colAl = ((lane >> 4) & 1) * 16;
    int rowBl = (lane & 7) + ((lane >> 4) & 1) * 8;
    int colBl = ((lane >> 3) & 1) * 16;
    uint32_t aRow[2], aMask[2];
#pragma unroll
    for (int ms = 0; ms < 2; ms++) {
        int row = wm * 32 + ms * 16 + rowAl;
        aRow[ms] = row * 128;
        aMask[ms] = (row & 7) << 4;
    }
    uint32_t bRow[4], bMask[4];
#pragma unroll
    for (int pp = 0; pp < 4; pp++) {
        int row = wn * 64 + pp * 16 + rowBl;
        bRow[pp] = row * 128;
        bMask[pp] = (row & 7) << 4;
    }

    float d[2][8][4];
#pragma unroll
    for (int ms = 0; ms < 2; ms++)
#pragma unroll
        for (int ns = 0; ns < 8; ns++)
#pragma unroll
            for (int j = 0; j < 4; j++) d[ms][ns][j] = 0.f;

    issue(0, 0);
    issue(1, 1);

    for (int c = 0; c < ENCH; c++) {
        int s = c % NSTG;
        CP_WAIT1();
        __syncthreads();
        if (c + 2 < ENCH) issue(c + 2, (c + 2) % NSTG);
        uint32_t bA = base + s * EST, bB = base + (NSTG + s) * EST;
#pragma unroll
        for (int kk = 0; kk < 4; kk++) {
            uint32_t kb = kk * 32;
            uint32_t af[2][4];
#pragma unroll
            for (int ms = 0; ms < 2; ms++)
                LDSM4(af[ms][0], af[ms][1], af[ms][2], af[ms][3],
                      bA + aRow[ms] + (((uint32_t)colAl + kb) ^ aMask[ms]));
            uint32_t bf[8][2];
#pragma unroll
            for (int pp = 0; pp < 4; pp++)
                LDSM4(bf[2 * pp][0], bf[2 * pp][1], bf[2 * pp + 1][0], bf[2 * pp + 1][1],
                      bB + bRow[pp] + (((uint32_t)colBl + kb) ^ bMask[pp]));
#pragma unroll
            for (int ms = 0; ms < 2; ms++)
#pragma unroll
                for (int ns = 0; ns < 8; ns++)
                    mma_f16(d[ms][ns], af[ms][0], af[ms][1], af[ms][2], af[ms][3],
                            bf[ns][0], bf[ns][1]);
        }
    }

    // Epilogue: tanh + q-dot; reduce over cols (4 lanes) via shfl, warps via smem
#pragma unroll
    for (int ms = 0; ms < 2; ms++) {
        float pr0 = 0.f, pr1 = 0.f;
#pragma unroll
        for (int ns = 0; ns < 8; ns++) {
            int n0 = wn * 64 + ns * 8 + 2 * laneq;
            float q0 = qs[n0], q1 = qs[n0 + 1];
            pr0 += tanhf(d[ms][ns][0]) * q0 + tanhf(d[ms][ns][1]) * q1;
            pr1 += tanhf(d[ms][ns][2]) * q0 + tanhf(d[ms][ns][3]) * q1;
        }
#pragma unroll
        for (int o = 1; o < 4; o <<= 1) {
            pr0 += __shfl_xor_sync(0xffffffffu, pr0, o);
            pr1 += __shfl_xor_sync(0xffffffffu, pr1, o);
        }
        if (laneq == 0) {
            int r = wm * 32 + ms * 16 + lane4;
            red[wn * 128 + r] = pr0;
            red[wn * 128 + r + 8] = pr1;
        }
    }
    __syncthreads();
    if (tid < 128) {
        int t = t0 + tid;
        if (t < Tv)
            ebuf[(size_t)(b * Hv + h) * Tv + t] = red[tid] + red[128 + tid];
    }
}

// ---------------------------------------------------------------------------
// Masked softmax over T, in place. w = softmax(SCALING*e) on t<len, 0 else.
// ---------------------------------------------------------------------------
__global__ __launch_bounds__(256) void softmax_kernel(float* __restrict__ wbuf,
                                                      const int* __restrict__ lens) {
    int bh = blockIdx.x;
    int b = bh / Hv;
    int len = get_len(lens, b);
    int tid = threadIdx.x;
    __shared__ float s[Tv];
    __shared__ float red[16];
    float* row = wbuf + (size_t)bh * Tv;
    for (int t = tid; t < Tv; t += 256) s[t] = row[t];
    __syncthreads();

    float m = -1e30f;
    for (int t = tid; t < len; t += 256) m = fmaxf(m, s[t]);
#pragma unroll
    for (int o = 16; o; o >>= 1) m = fmaxf(m, __shfl_xor_sync(0xffffffffu, m, o));
    if ((tid & 31) == 0) red[tid >> 5] = m;
    __syncthreads();
    m = red[0];
#pragma unroll
    for (int i = 1; i < 8; i++) m = fmaxf(m, red[i]);
    float M = SCALING * m;

    float lsum = 0.f;
    for (int t = tid; t < len; t += 256) lsum += expf(SCALING * s[t] - M);
#pragma unroll
    for (int o = 16; o; o >>= 1) lsum += __shfl_xor_sync(0xffffffffu, lsum, o);
    if ((tid & 31) == 0) red[8 + (tid >> 5)] = lsum;
    __syncthreads();
    float total = 0.f;
#pragma unroll
    for (int i = 0; i < 8; i++) total += red[8 + i];
    float inv = 1.f / total;

    for (int t = tid; t < Tv; t += 256)
        row[t] = (t < len) ? expf(SCALING * s[t] - M) * inv : 0.f;
}

// ---------------------------------------------------------------------------
// u partials, vectorized (4 d per thread), unroll 4 over t for MLP.
// ---------------------------------------------------------------------------
__global__ __launch_bounds__(256) void u_kernel(const float* __restrict__ wbuf,
                                                const int* __restrict__ lens) {
    int tc = blockIdx.x, b = blockIdx.y;
    int d0 = threadIdx.x * 4;
    int len = get_len(lens, b);
    int t0 = tc * 128;
    float* up = g_up + (((size_t)tc * Bv + b) * Hv) * Ev + d0;
    if (t0 >= len) {
#pragma unroll
        for (int h = 0; h < Hv; h++)
            *(float4*)(up + (size_t)h * Ev) = make_float4(0.f, 0.f, 0.f, 0.f);
        return;
    }
    int tmax = min(min(128, Tv - t0), len - t0);
    __shared__ float ws[Hv][128];
#pragma unroll
    for (int r = 0; r < 4; r++) {
        int f = r * 256 + threadIdx.x;
        int h = f >> 7, tt = f & 127;
        int t = t0 + tt;
        ws[h][tt] = (t < Tv) ? wbuf[((size_t)(b * Hv + h)) * Tv + t] : 0.f;
    }
    __syncthreads();

    float acc[Hv][4];
#pragma unroll
    for (int h = 0; h < Hv; h++)
#pragma unroll
        for (int j = 0; j < 4; j++) acc[h][j] = 0.f;

    const __half* A = g_enc16 + (size_t)b * Tv * Ev + (size_t)t0 * Ev + d0;
#pragma unroll 4
    for (int tt = 0; tt < tmax; tt++) {
        uint2 raw = *(const uint2*)(A + (size_t)tt * Ev);
        float2 x01 = __half22float2(*(__half2*)&raw.x);
        float2 x23 = __half22float2(*(__half2*)&raw.y);
#pragma unroll
        for (int h = 0; h < Hv; h++) {
            float w = ws[h][tt];
            acc[h][0] += w * x01.x;
            acc[h][1] += w * x01.y;
            acc[h][2] += w * x23.x;
            acc[h][3] += w * x23.y;
        }
    }
#pragma unroll
    for (int h = 0; h < Hv; h++)
        *(float4*)(up + (size_t)h * Ev) =
            make_float4(acc[h][0], acc[h][1], acc[h][2], acc[h][3]);
}

// ---------------------------------------------------------------------------
// c[b,h,v] = u[b,h,:]·Wv[h,:,v]; 4 accumulators for MLP.
// ---------------------------------------------------------------------------
__global__ __launch_bounds__(128) void c_kernel(const float* __restrict__ Wv) {
    int h = blockIdx.x, b = blockIdx.y;
    int v = threadIdx.x;
    __shared__ float us[Ev];
    for (int i = v; i < Ev; i += 128) {
        float s0 = 0.f, s1 = 0.f;
#pragma unroll
        for (int tc = 0; tc < TCHUNK; tc += 2) {
            s0 += g_up[(((size_t)tc * Bv + b) * Hv + h) * Ev + i];
            s1 += g_up[(((size_t)(tc + 1) * Bv + b) * Hv + h) * Ev + i];
        }
        us[i] = s0 + s1;
    }
    __syncthreads();
    const float* W = Wv + (size_t)h * Ev * DVv + v;
    float a[4] = {0.f, 0.f, 0.f, 0.f};
#pragma unroll 4
    for (int d = 0; d < Ev; d += 4) {
        a[0] += us[d] * W[(size_t)d * DVv];
        a[1] += us[d + 1] * W[(size_t)(d + 1) * DVv];
        a[2] += us[d + 2] * W[(size_t)(d + 2) * DVv];
        a[3] += us[d + 3] * W[(size_t)(d + 3) * DVv];
    }
    g_c[(b * Hv + h) * DVv + v] = (a[0] + a[1]) + (a[2] + a[3]);
}

// ---------------------------------------------------------------------------
// out[b,e] = c_flat[b,:]·Wo[:,e]; 4 accumulators for MLP.
// ---------------------------------------------------------------------------
__global__ __launch_bounds__(256) void out_kernel(const float* __restrict__ Wo,
                                                  float* __restrict__ out) {
    int chunk = blockIdx.x, b = blockIdx.y;
    int e = chunk * 256 + threadIdx.x;
    __shared__ float cs[Hv * DVv];
    for (int i = threadIdx.x; i < Hv * DVv; i += 256) cs[i] = g_c[b * Hv * DVv + i];
    __syncthreads();
    float a[4] = {0.f, 0.f, 0.f, 0.f};
#pragma unroll 4
    for (int i = 0; i < Hv * DVv; i += 4) {
        a[0] += cs[i] * Wo[(size_t)i * Ev + e];
        a[1] += cs[i + 1] * Wo[(size_t)(i + 1) * Ev + e];
        a[2] += cs[i + 2] * Wo[(size_t)(i + 2) * Ev + e];
        a[3] += cs[i + 3] * Wo[(size_t)(i + 3) * Ev + e];
    }
    out[(size_t)b * Ev + e] = (a[0] + a[1]) + (a[2] + a[3]);
}

// ---------------------------------------------------------------------------
extern "C" void kernel_launch(void* const* d_in, const int* in_sizes, int n_in,
                              void* d_out, int out_size) {
    const float* enc   = (const float*)d_in[0];
    const int*   lens  = (const int*)d_in[1];
    const float* dec_z = (const float*)d_in[2];
    const float* Wq    = (const float*)d_in[3];
    const float* bq    = (const float*)d_in[4];
    const float* Wk    = (const float*)d_in[5];
    const float* Wv    = (const float*)d_in[6];
    const float* Wo    = (const float*)d_in[7];

    float* out  = (float*)d_out;   // (B,E)
    float* wbuf = out + Bv * Ev;   // (B,H,T): e logits, then w in place

    static int inited = 0;
    if (!inited) {
        cudaFuncSetAttribute(e_tc_kernel, cudaFuncAttributeMaxDynamicSharedMemorySize, E_SMEM);
        inited = 1;
    }

    prep_kernel<<<PREPB, 256>>>(enc, lens, Wk, dec_z, Wq, bq);
    e_tc_kernel<<<dim3(Hv, (Tv + 127) / 128, Bv), 256, E_SMEM>>>(wbuf, lens);
    softmax_kernel<<<Bv * Hv, 256>>>(wbuf, lens);
    u_kernel<<<dim3(TCHUNK, Bv), 256>>>(wbuf, lens);
    c_kernel<<<dim3(Hv, Bv), 128>>>(Wv);
    out_kernel<<<dim3(Ev / 256, Bv), 256>>>(Wo, out);
}

// round 13
// speedup vs baseline: 1.2457x; 1.0807x over previous
#include <cuda_runtime.h>
#include <cuda_fp16.h>
#include <cstdint>

#define Bv 32
#define Tv 1500
#define Ev 1024
#define Hv 8
#define DKv 128
#define DVv 128
#define Dv 1024
#define SCALING 0.088388347648318447f  // 1/sqrt(128)
#define TCHUNK 24
#define TCW 64                         // t rows per u-chunk

// Scratch (no allocations allowed)
__device__ float g_q[Bv * Hv * DKv];            // tanh(dec_z@Wq + bq)
__device__ float g_c[Bv * Hv * DVv];            // u @ Wv
__device__ float g_up[(size_t)Bv * Hv * TCHUNK * Ev];  // u partials [b][h][tc][d]
__device__ __half g_enc16[(size_t)Bv * Tv * Ev];   // enc in fp16 (98.3 MB)
__device__ __half g_wkT16[(size_t)Hv * DKv * Ev];  // Wk^T in fp16: [h][n][e]

// ---------------------------------------------------------------------------
// PTX helpers (sm_80-level only; tcgen05 is rejected by this harness target)
// ---------------------------------------------------------------------------
__device__ __forceinline__ uint32_t smem_u32(const void* p) {
    uint32_t a;
    asm("{ .reg .u64 t; cvta.to.shared.u64 t, %1; cvt.u32.u64 %0, t; }" : "=r"(a) : "l"(p));
    return a;
}
#define CP16(sm, gm, sz) \
    asm volatile("cp.async.cg.shared.global [%0], [%1], 16, %2;" ::"r"(sm), "l"(gm), "r"(sz) : "memory")
#define CP_COMMIT() asm volatile("cp.async.commit_group;" ::: "memory")
#define CP_WAIT1() asm volatile("cp.async.wait_group 1;" ::: "memory")
#define LDSM4(r0, r1, r2, r3, a)                                             \
    asm volatile("ldmatrix.sync.aligned.m8n8.x4.shared.b16 {%0,%1,%2,%3}, [%4];" \
                 : "=r"(r0), "=r"(r1), "=r"(r2), "=r"(r3) : "r"(a))

__device__ __forceinline__ void mma_f16(float* d, uint32_t a0, uint32_t a1, uint32_t a2,
                                        uint32_t a3, uint32_t b0, uint32_t b1) {
    asm volatile(
        "mma.sync.aligned.m16n8k16.row.col.f32.f16.f16.f32 "
        "{%0,%1,%2,%3}, {%4,%5,%6,%7}, {%8,%9}, {%0,%1,%2,%3};"
        : "+f"(d[0]), "+f"(d[1]), "+f"(d[2]), "+f"(d[3])
        : "r"(a0), "r"(a1), "r"(a2), "r"(a3), "r"(b0), "r"(b1));
}
__device__ __forceinline__ uint32_t sw128(uint32_t o) { return o ^ ((o >> 3) & 0x70); }

// ---------------------------------------------------------------------------
// Length read with dtype sniff (int64 declared, int32 in practice)
// ---------------------------------------------------------------------------
__device__ __forceinline__ int get_len(const int* __restrict__ L, int b) {
    bool is64 = (L[1] == 0);
    return is64 ? L[2 * b] : L[b];
}

// ---------------------------------------------------------------------------
// Fused prep: enc->fp16 (clipped), WkT fp16 transpose, q projection.
// ---------------------------------------------------------------------------
#define ENCB ((Bv * Tv * Ev) / (256 * 8))   // 24000
#define WKTB ((Ev / 32) * (DKv / 32) * Hv)  // 1024
#define QB ((Hv / 2) * Bv)                  // 128
#define PREPB (ENCB + WKTB + QB)

__global__ __launch_bounds__(256) void prep_kernel(const float* __restrict__ enc,
                                                   const int* __restrict__ lens,
                                                   const float* __restrict__ Wk,
                                                   const float* __restrict__ dec_z,
                                                   const float* __restrict__ Wq,
                                                   const float* __restrict__ bq) {
    int bx = blockIdx.x;
    if (bx < ENCB) {
        size_t base = ((size_t)bx * 256 + threadIdx.x) * 8;
        int t = (int)((base / Ev) % Tv);
        int b = (int)(base / ((size_t)Ev * Tv));
        int len = get_len(lens, b);
        if (t >= ((len + 127) & ~127)) return;
        float4 v0 = *(const float4*)(enc + base);
        float4 v1 = *(const float4*)(enc + base + 4);
        __half2 h[4];
        h[0] = __floats2half2_rn(v0.x, v0.y);
        h[1] = __floats2half2_rn(v0.z, v0.w);
        h[2] = __floats2half2_rn(v1.x, v1.y);
        h[3] = __floats2half2_rn(v1.z, v1.w);
        *(uint4*)(g_enc16 + base) = *(uint4*)h;
    } else if (bx < ENCB + WKTB) {
        __shared__ float tile[32][33];
        int idx = bx - ENCB;
        int e0 = (idx & 31) * 32;
        int n0 = ((idx >> 5) & 3) * 32;
        int h = idx >> 7;
        int tx = threadIdx.x & 31, ty = threadIdx.x >> 5;
        for (int i = ty; i < 32; i += 8)
            tile[i][tx] = Wk[((size_t)h * Ev + e0 + i) * DKv + n0 + tx];
        __syncthreads();
        for (int i = ty; i < 32; i += 8)
            g_wkT16[((size_t)h * DKv + n0 + i) * Ev + e0 + tx] = __float2half_rn(tile[tx][i]);
    } else {
        __shared__ float zs[Dv];
        int idx = bx - ENCB - WKTB;
        int b = idx >> 2;
        int h = (idx & 3) * 2 + (threadIdx.x >> 7);
        int k = threadIdx.x & 127;
        for (int i = threadIdx.x; i < Dv; i += 256) zs[i] = dec_z[b * Dv + i];
        __syncthreads();
        const float* W = Wq + (size_t)h * Dv * DKv + k;
        float a[4] = {0.f, 0.f, 0.f, 0.f};
#pragma unroll 4
        for (int d = 0; d < Dv; d += 4) {
            a[0] += zs[d] * W[(size_t)d * DKv];
            a[1] += zs[d + 1] * W[(size_t)(d + 1) * DKv];
            a[2] += zs[d + 2] * W[(size_t)(d + 2) * DKv];
            a[3] += zs[d + 3] * W[(size_t)(d + 3) * DKv];
        }
        g_q[(b * Hv + h) * DKv + k] =
            tanhf(bq[h * DKv + k] + (a[0] + a[1]) + (a[2] + a[3]));
    }
}

// ---------------------------------------------------------------------------
// e[b,h,t]: fp16 m16n8k16 GEMM (R9 config: 128-t tile, 2 CTA/SM, 128 regs).
// ---------------------------------------------------------------------------
#define ECH 64
#define ENCH (Ev / ECH)
#define EST 16384
#define NSTG 3
#define OFF_QS (2 * NSTG * EST)
#define OFF_RED (OFF_QS + 512)
#define E_SMEM (OFF_RED + 1024)

__global__ __launch_bounds__(256, 2) void e_tc_kernel(float* __restrict__ ebuf,
                                                      const int* __restrict__ lens) {
    extern __shared__ __align__(16) char dsm[];
    float* qs = (float*)(dsm + OFF_QS);
    float* red = (float*)(dsm + OFF_RED);

    int tid = threadIdx.x, wid = tid >> 5, lane = tid & 31;
    int h = blockIdx.x, tile = blockIdx.y, b = blockIdx.z;
    int t0 = tile * 128;
    int len = get_len(lens, b);
    if (t0 >= len) return;

    int wm = wid & 3, wn = wid >> 2;
    int lane4 = lane >> 2, laneq = lane & 3;

    if (tid < DKv) qs[tid] = g_q[(b * Hv + h) * DKv + tid];

    const __half* A = g_enc16 + (size_t)b * Tv * Ev;
    const __half* Wt = g_wkT16 + (size_t)h * DKv * Ev;

    uint32_t base = smem_u32(dsm);

    uint32_t swz[4];
    const __half* pA[4];
    const __half* pB[4];
    uint32_t szA[4];
#pragma unroll
    for (int r = 0; r < 4; r++) {
        int idx = r * 256 + tid;
        int row = idx >> 3, seg = idx & 7;
        swz[r] = sw128(row * 128 + seg * 16);
        int t = t0 + row;
        szA[r] = (t < Tv) ? 16u : 0u;
        pA[r] = A + (size_t)t * Ev + seg * 8;
        pB[r] = Wt + (size_t)row * Ev + seg * 8;
    }

    auto issue = [&](int c, int s) {
        int k0 = c * ECH;
        uint32_t bA = base + s * EST, bB = base + (NSTG + s) * EST;
#pragma unroll
        for (int r = 0; r < 4; r++) CP16(bA + swz[r], pA[r] + k0, szA[r]);
#pragma unroll
        for (int r = 0; r < 4; r++) CP16(bB + swz[r], pB[r] + k0, 16u);
        CP_COMMIT();
    };

    int rowAl = (lane & 7) + ((lane >> 3) & 1) * 8;
    int colAl = ((lane >> 4) & 1) * 16;
    int rowBl = (lane & 7) + ((lane >> 4) & 1) * 8;
    int colBl = ((lane >> 3) & 1) * 16;
    uint32_t aRow[2], aMask[2];
#pragma unroll
    for (int ms = 0; ms < 2; ms++) {
        int row = wm * 32 + ms * 16 + rowAl;
        aRow[ms] = row * 128;
        aMask[ms] = (row & 7) << 4;
    }
    uint32_t bRow[4], bMask[4];
#pragma unroll
    for (int pp = 0; pp < 4; pp++) {
        int row = wn * 64 + pp * 16 + rowBl;
        bRow[pp] = row * 128;
        bMask[pp] = (row & 7) << 4;
    }

    float d[2][8][4];
#pragma unroll
    for (int ms = 0; ms < 2; ms++)
#pragma unroll
        for (int ns = 0; ns < 8; ns++)
#pragma unroll
            for (int j = 0; j < 4; j++) d[ms][ns][j] = 0.f;

    issue(0, 0);
    issue(1, 1);

    for (int c = 0; c < ENCH; c++) {
        int s = c % NSTG;
        CP_WAIT1();
        __syncthreads();
        if (c + 2 < ENCH) issue(c + 2, (c + 2) % NSTG);
        uint32_t bA = base + s * EST, bB = base + (NSTG + s) * EST;
#pragma unroll
        for (int kk = 0; kk < 4; kk++) {
            uint32_t kb = kk * 32;
            uint32_t af[2][4];
#pragma unroll
            for (int ms = 0; ms < 2; ms++)
                LDSM4(af[ms][0], af[ms][1], af[ms][2], af[ms][3],
                      bA + aRow[ms] + (((uint32_t)colAl + kb) ^ aMask[ms]));
            uint32_t bf[8][2];
#pragma unroll
            for (int pp = 0; pp < 4; pp++)
                LDSM4(bf[2 * pp][0], bf[2 * pp][1], bf[2 * pp + 1][0], bf[2 * pp + 1][1],
                      bB + bRow[pp] + (((uint32_t)colBl + kb) ^ bMask[pp]));
#pragma unroll
            for (int ms = 0; ms < 2; ms++)
#pragma unroll
                for (int ns = 0; ns < 8; ns++)
                    mma_f16(d[ms][ns], af[ms][0], af[ms][1], af[ms][2], af[ms][3],
                            bf[ns][0], bf[ns][1]);
        }
    }

#pragma unroll
    for (int ms = 0; ms < 2; ms++) {
        float pr0 = 0.f, pr1 = 0.f;
#pragma unroll
        for (int ns = 0; ns < 8; ns++) {
            int n0 = wn * 64 + ns * 8 + 2 * laneq;
            float q0 = qs[n0], q1 = qs[n0 + 1];
            pr0 += tanhf(d[ms][ns][0]) * q0 + tanhf(d[ms][ns][1]) * q1;
            pr1 += tanhf(d[ms][ns][2]) * q0 + tanhf(d[ms][ns][3]) * q1;
        }
#pragma unroll
        for (int o = 1; o < 4; o <<= 1) {
            pr0 += __shfl_xor_sync(0xffffffffu, pr0, o);
            pr1 += __shfl_xor_sync(0xffffffffu, pr1, o);
        }
        if (laneq == 0) {
            int r = wm * 32 + ms * 16 + lane4;
            red[wn * 128 + r] = pr0;
            red[wn * 128 + r + 8] = pr1;
        }
    }
    __syncthreads();
    if (tid < 128) {
        int t = t0 + tid;
        if (t < Tv)
            ebuf[(size_t)(b * Hv + h) * Tv + t] = red[tid] + red[128 + tid];
    }
}

// ---------------------------------------------------------------------------
// Masked softmax over T, in place.
// ---------------------------------------------------------------------------
__global__ __launch_bounds__(256) void softmax_kernel(float* __restrict__ wbuf,
                                                      const int* __restrict__ lens) {
    int bh = blockIdx.x;
    int b = bh / Hv;
    int len = get_len(lens, b);
    int tid = threadIdx.x;
    __shared__ float s[Tv];
    __shared__ float red[16];
    float* row = wbuf + (size_t)bh * Tv;
    for (int t = tid; t < Tv; t += 256) s[t] = row[t];
    __syncthreads();

    float m = -1e30f;
    for (int t = tid; t < len; t += 256) m = fmaxf(m, s[t]);
#pragma unroll
    for (int o = 16; o; o >>= 1) m = fmaxf(m, __shfl_xor_sync(0xffffffffu, m, o));
    if ((tid & 31) == 0) red[tid >> 5] = m;
    __syncthreads();
    m = red[0];
#pragma unroll
    for (int i = 1; i < 8; i++) m = fmaxf(m, red[i]);
    float M = SCALING * m;

    float lsum = 0.f;
    for (int t = tid; t < len; t += 256) lsum += expf(SCALING * s[t] - M);
#pragma unroll
    for (int o = 16; o; o >>= 1) lsum += __shfl_xor_sync(0xffffffffu, lsum, o);
    if ((tid & 31) == 0) red[8 + (tid >> 5)] = lsum;
    __syncthreads();
    float total = 0.f;
#pragma unroll
    for (int i = 0; i < 8; i++) total += red[8 + i];
    float inv = 1.f / total;

    for (int t = tid; t < Tv; t += 256)
        row[t] = (t < len) ? expf(SCALING * s[t] - M) * inv : 0.f;
}

// ---------------------------------------------------------------------------
// u partials: 64-t chunks (TCHUNK=24, 768 CTAs) for more latency overlap.
// g_up layout [b][h][tc][d] so c_kernel's reduction reads 4KB-strided.
// ---------------------------------------------------------------------------
__global__ __launch_bounds__(256) void u_kernel(const float* __restrict__ wbuf,
                                                const int* __restrict__ lens) {
    int tc = blockIdx.x, b = blockIdx.y;
    int d0 = threadIdx.x * 4;
    int len = get_len(lens, b);
    int t0 = tc * TCW;
    float* up = g_up + (((size_t)b * Hv) * TCHUNK + tc) * Ev + d0;
    if (t0 >= len) {
#pragma unroll
        for (int h = 0; h < Hv; h++)
            *(float4*)(up + (size_t)h * TCHUNK * Ev) = make_float4(0.f, 0.f, 0.f, 0.f);
        return;
    }
    int tmax = min(min(TCW, Tv - t0), len - t0);
    __shared__ float ws[Hv][TCW];
#pragma unroll
    for (int r = 0; r < 2; r++) {
        int f = r * 256 + threadIdx.x;
        int h = f >> 6, tt = f & 63;
        int t = t0 + tt;
        ws[h][tt] = (t < Tv) ? wbuf[((size_t)(b * Hv + h)) * Tv + t] : 0.f;
    }
    __syncthreads();

    float acc[Hv][4];
#pragma unroll
    for (int h = 0; h < Hv; h++)
#pragma unroll
        for (int j = 0; j < 4; j++) acc[h][j] = 0.f;

    const __half* A = g_enc16 + (size_t)b * Tv * Ev + (size_t)t0 * Ev + d0;
#pragma unroll 4
    for (int tt = 0; tt < tmax; tt++) {
        uint2 raw = *(const uint2*)(A + (size_t)tt * Ev);
        float2 x01 = __half22float2(*(__half2*)&raw.x);
        float2 x23 = __half22float2(*(__half2*)&raw.y);
#pragma unroll
        for (int h = 0; h < Hv; h++) {
            float w = ws[h][tt];
            acc[h][0] += w * x01.x;
            acc[h][1] += w * x01.y;
            acc[h][2] += w * x23.x;
            acc[h][3] += w * x23.y;
        }
    }
#pragma unroll
    for (int h = 0; h < Hv; h++)
        *(float4*)(up + (size_t)h * TCHUNK * Ev) =
            make_float4(acc[h][0], acc[h][1], acc[h][2], acc[h][3]);
}

// ---------------------------------------------------------------------------
// c[b,h,v] = u[b,h,:]·Wv[h,:,v]; 256 thr: 2-way K split + smem combine.
// ---------------------------------------------------------------------------
__global__ __launch_bounds__(256) void c_kernel(const float* __restrict__ Wv) {
    int h = blockIdx.x, b = blockIdx.y;
    int half = threadIdx.x >> 7, v = threadIdx.x & 127;
    __shared__ float us[Ev];
    __shared__ float ps[2][DVv];
    const float* upb = g_up + ((size_t)(b * Hv + h)) * TCHUNK * Ev;
    for (int i = threadIdx.x; i < Ev; i += 256) {
        float s0 = 0.f, s1 = 0.f;
#pragma unroll
        for (int tc = 0; tc < TCHUNK; tc += 2) {
            s0 += upb[(size_t)tc * Ev + i];
            s1 += upb[(size_t)(tc + 1) * Ev + i];
        }
        us[i] = s0 + s1;
    }
    __syncthreads();
    const float* W = Wv + (size_t)h * Ev * DVv + v;
    int dbeg = half * 512;
    float a[4] = {0.f, 0.f, 0.f, 0.f};
#pragma unroll 4
    for (int d = dbeg; d < dbeg + 512; d += 4) {
        a[0] += us[d] * W[(size_t)d * DVv];
        a[1] += us[d + 1] * W[(size_t)(d + 1) * DVv];
        a[2] += us[d + 2] * W[(size_t)(d + 2) * DVv];
        a[3] += us[d + 3] * W[(size_t)(d + 3) * DVv];
    }
    ps[half][v] = (a[0] + a[1]) + (a[2] + a[3]);
    __syncthreads();
    if (threadIdx.x < DVv)
        g_c[(b * Hv + h) * DVv + threadIdx.x] = ps[0][threadIdx.x] + ps[1][threadIdx.x];
}

// ---------------------------------------------------------------------------
// out[b,e] = c_flat[b,:]·Wo[:,e]; 512 thr: 2-way K split + smem combine.
// ---------------------------------------------------------------------------
__global__ __launch_bounds__(512) void out_kernel(const float* __restrict__ Wo,
                                                  float* __restrict__ out) {
    int chunk = blockIdx.x, b = blockIdx.y;
    int half = threadIdx.x >> 8, el = threadIdx.x & 255;
    int e = chunk * 256 + el;
    __shared__ float cs[Hv * DVv];
    __shared__ float po[2][256];
    for (int i = threadIdx.x; i < Hv * DVv; i += 512) cs[i] = g_c[b * Hv * DVv + i];
    __syncthreads();
    int ibeg = half * 512;
    float a[4] = {0.f, 0.f, 0.f, 0.f};
#pragma unroll 4
    for (int i = ibeg; i < ibeg + 512; i += 4) {
        a[0] += cs[i] * Wo[(size_t)i * Ev + e];
        a[1] += cs[i + 1] * Wo[(size_t)(i + 1) * Ev + e];
        a[2] += cs[i + 2] * Wo[(size_t)(i + 2) * Ev + e];
        a[3] += cs[i + 3] * Wo[(size_t)(i + 3) * Ev + e];
    }
    po[half][el] = (a[0] + a[1]) + (a[2] + a[3]);
    __syncthreads();
    if (threadIdx.x < 256)
        out[(size_t)b * Ev + e] = po[0][el] + po[1][el];
}

// ---------------------------------------------------------------------------
extern "C" void kernel_launch(void* const* d_in, const int* in_sizes, int n_in,
                              void* d_out, int out_size) {
    const float* enc   = (const float*)d_in[0];
    const int*   lens  = (const int*)d_in[1];
    const float* dec_z = (const float*)d_in[2];
    const float* Wq    = (const float*)d_in[3];
    const float* bq    = (const float*)d_in[4];
    const float* Wk    = (const float*)d_in[5];
    const float* Wv    = (const float*)d_in[6];
    const float* Wo    = (const float*)d_in[7];

    float* out  = (float*)d_out;   // (B,E)
    float* wbuf = out + Bv * Ev;   // (B,H,T): e logits, then w in place

    static int inited = 0;
    if (!inited) {
        cudaFuncSetAttribute(e_tc_kernel, cudaFuncAttributeMaxDynamicSharedMemorySize, E_SMEM);
        inited = 1;
    }

    prep_kernel<<<PREPB, 256>>>(enc, lens, Wk, dec_z, Wq, bq);
    e_tc_kernel<<<dim3(Hv, (Tv + 127) / 128, Bv), 256, E_SMEM>>>(wbuf, lens);
    softmax_kernel<<<Bv * Hv, 256>>>(wbuf, lens);
    u_kernel<<<dim3(TCHUNK, Bv), 256>>>(wbuf, lens);
    c_kernel<<<dim3(Hv, Bv), 256>>>(Wv);
    out_kernel<<<dim3(Ev / 256, Bv), 512>>>(Wo, out);
}

// round 14
// speedup vs baseline: 1.2567x; 1.0089x over previous
#include <cuda_runtime.h>
#include <cuda_fp16.h>
#include <cstdint>

#define Bv 32
#define Tv 1500
#define Ev 1024
#define Hv 8
#define DKv 128
#define DVv 128
#define Dv 1024
#define SCALING 0.088388347648318447f  // 1/sqrt(128)
#define TCHUNK 12
#define TCW 128                        // t rows per u-chunk

// Scratch (no allocations allowed)
__device__ float g_q[Bv * Hv * DKv];            // tanh(dec_z@Wq + bq)
__device__ float g_c[Bv * Hv * DVv];            // u @ Wv
__device__ float g_up[(size_t)Bv * Hv * TCHUNK * Ev];  // u partials [b][h][tc][d]
__device__ __half g_enc16[(size_t)Bv * Tv * Ev];   // enc in fp16 (98.3 MB)
__device__ __half g_wkT16[(size_t)Hv * DKv * Ev];  // Wk^T in fp16: [h][n][e]

// ---------------------------------------------------------------------------
// PTX helpers (sm_80-level only; tcgen05 is rejected by this harness target)
// ---------------------------------------------------------------------------
__device__ __forceinline__ uint32_t smem_u32(const void* p) {
    uint32_t a;
    asm("{ .reg .u64 t; cvta.to.shared.u64 t, %1; cvt.u32.u64 %0, t; }" : "=r"(a) : "l"(p));
    return a;
}
#define CP16(sm, gm, sz) \
    asm volatile("cp.async.cg.shared.global [%0], [%1], 16, %2;" ::"r"(sm), "l"(gm), "r"(sz) : "memory")
#define CP_COMMIT() asm volatile("cp.async.commit_group;" ::: "memory")
#define CP_WAIT1() asm volatile("cp.async.wait_group 1;" ::: "memory")
#define LDSM4(r0, r1, r2, r3, a)                                             \
    asm volatile("ldmatrix.sync.aligned.m8n8.x4.shared.b16 {%0,%1,%2,%3}, [%4];" \
                 : "=r"(r0), "=r"(r1), "=r"(r2), "=r"(r3) : "r"(a))

__device__ __forceinline__ void mma_f16(float* d, uint32_t a0, uint32_t a1, uint32_t a2,
                                        uint32_t a3, uint32_t b0, uint32_t b1) {
    asm volatile(
        "mma.sync.aligned.m16n8k16.row.col.f32.f16.f16.f32 "
        "{%0,%1,%2,%3}, {%4,%5,%6,%7}, {%8,%9}, {%0,%1,%2,%3};"
        : "+f"(d[0]), "+f"(d[1]), "+f"(d[2]), "+f"(d[3])
        : "r"(a0), "r"(a1), "r"(a2), "r"(a3), "r"(b0), "r"(b1));
}
__device__ __forceinline__ uint32_t sw128(uint32_t o) { return o ^ ((o >> 3) & 0x70); }

// ---------------------------------------------------------------------------
// Length read with dtype sniff (int64 declared, int32 in practice)
// ---------------------------------------------------------------------------
__device__ __forceinline__ int get_len(const int* __restrict__ L, int b) {
    bool is64 = (L[1] == 0);
    return is64 ? L[2 * b] : L[b];
}

// ---------------------------------------------------------------------------
// Fused prep: enc->fp16 (clipped), WkT fp16 transpose, q projection.
// ---------------------------------------------------------------------------
#define ENCB ((Bv * Tv * Ev) / (256 * 8))   // 24000
#define WKTB ((Ev / 32) * (DKv / 32) * Hv)  // 1024
#define QB ((Hv / 2) * Bv)                  // 128
#define PREPB (ENCB + WKTB + QB)

__global__ __launch_bounds__(256) void prep_kernel(const float* __restrict__ enc,
                                                   const int* __restrict__ lens,
                                                   const float* __restrict__ Wk,
                                                   const float* __restrict__ dec_z,
                                                   const float* __restrict__ Wq,
                                                   const float* __restrict__ bq) {
    int bx = blockIdx.x;
    if (bx < ENCB) {
        size_t base = ((size_t)bx * 256 + threadIdx.x) * 8;
        int t = (int)((base / Ev) % Tv);
        int b = (int)(base / ((size_t)Ev * Tv));
        int len = get_len(lens, b);
        if (t >= ((len + 127) & ~127)) return;
        float4 v0 = *(const float4*)(enc + base);
        float4 v1 = *(const float4*)(enc + base + 4);
        __half2 h[4];
        h[0] = __floats2half2_rn(v0.x, v0.y);
        h[1] = __floats2half2_rn(v0.z, v0.w);
        h[2] = __floats2half2_rn(v1.x, v1.y);
        h[3] = __floats2half2_rn(v1.z, v1.w);
        *(uint4*)(g_enc16 + base) = *(uint4*)h;
    } else if (bx < ENCB + WKTB) {
        __shared__ float tile[32][33];
        int idx = bx - ENCB;
        int e0 = (idx & 31) * 32;
        int n0 = ((idx >> 5) & 3) * 32;
        int h = idx >> 7;
        int tx = threadIdx.x & 31, ty = threadIdx.x >> 5;
        for (int i = ty; i < 32; i += 8)
            tile[i][tx] = Wk[((size_t)h * Ev + e0 + i) * DKv + n0 + tx];
        __syncthreads();
        for (int i = ty; i < 32; i += 8)
            g_wkT16[((size_t)h * DKv + n0 + i) * Ev + e0 + tx] = __float2half_rn(tile[tx][i]);
    } else {
        __shared__ float zs[Dv];
        int idx = bx - ENCB - WKTB;
        int b = idx >> 2;
        int h = (idx & 3) * 2 + (threadIdx.x >> 7);
        int k = threadIdx.x & 127;
        for (int i = threadIdx.x; i < Dv; i += 256) zs[i] = dec_z[b * Dv + i];
        __syncthreads();
        const float* W = Wq + (size_t)h * Dv * DKv + k;
        float a[4] = {0.f, 0.f, 0.f, 0.f};
#pragma unroll 4
        for (int d = 0; d < Dv; d += 4) {
            a[0] += zs[d] * W[(size_t)d * DKv];
            a[1] += zs[d + 1] * W[(size_t)(d + 1) * DKv];
            a[2] += zs[d + 2] * W[(size_t)(d + 2) * DKv];
            a[3] += zs[d + 3] * W[(size_t)(d + 3) * DKv];
        }
        g_q[(b * Hv + h) * DKv + k] =
            tanhf(bq[h * DKv + k] + (a[0] + a[1]) + (a[2] + a[3]));
    }
}

// ---------------------------------------------------------------------------
// e[b,h,t]: fp16 m16n8k16 GEMM (R9 config: 128-t tile, 2 CTA/SM, 128 regs).
// ---------------------------------------------------------------------------
#define ECH 64
#define ENCH (Ev / ECH)
#define EST 16384
#define NSTG 3
#define OFF_QS (2 * NSTG * EST)
#define OFF_RED (OFF_QS + 512)
#define E_SMEM (OFF_RED + 1024)

__global__ __launch_bounds__(256, 2) void e_tc_kernel(float* __restrict__ ebuf,
                                                      const int* __restrict__ lens) {
    extern __shared__ __align__(16) char dsm[];
    float* qs = (float*)(dsm + OFF_QS);
    float* red = (float*)(dsm + OFF_RED);

    int tid = threadIdx.x, wid = tid >> 5, lane = tid & 31;
    int h = blockIdx.x, tile = blockIdx.y, b = blockIdx.z;
    int t0 = tile * 128;
    int len = get_len(lens, b);
    if (t0 >= len) return;

    int wm = wid & 3, wn = wid >> 2;
    int lane4 = lane >> 2, laneq = lane & 3;

    if (tid < DKv) qs[tid] = g_q[(b * Hv + h) * DKv + tid];

    const __half* A = g_enc16 + (size_t)b * Tv * Ev;
    const __half* Wt = g_wkT16 + (size_t)h * DKv * Ev;

    uint32_t base = smem_u32(dsm);

    uint32_t swz[4];
    const __half* pA[4];
    const __half* pB[4];
    uint32_t szA[4];
#pragma unroll
    for (int r = 0; r < 4; r++) {
        int idx = r * 256 + tid;
        int row = idx >> 3, seg = idx & 7;
        swz[r] = sw128(row * 128 + seg * 16);
        int t = t0 + row;
        szA[r] = (t < Tv) ? 16u : 0u;
        pA[r] = A + (size_t)t * Ev + seg * 8;
        pB[r] = Wt + (size_t)row * Ev + seg * 8;
    }

    auto issue = [&](int c, int s) {
        int k0 = c * ECH;
        uint32_t bA = base + s * EST, bB = base + (NSTG + s) * EST;
#pragma unroll
        for (int r = 0; r < 4; r++) CP16(bA + swz[r], pA[r] + k0, szA[r]);
#pragma unroll
        for (int r = 0; r < 4; r++) CP16(bB + swz[r], pB[r] + k0, 16u);
        CP_COMMIT();
    };

    int rowAl = (lane & 7) + ((lane >> 3) & 1) * 8;
    int colAl = ((lane >> 4) & 1) * 16;
    int rowBl = (lane & 7) + ((lane >> 4) & 1) * 8;
    int colBl = ((lane >> 3) & 1) * 16;
    uint32_t aRow[2], aMask[2];
#pragma unroll
    for (int ms = 0; ms < 2; ms++) {
        int row = wm * 32 + ms * 16 + rowAl;
        aRow[ms] = row * 128;
        aMask[ms] = (row & 7) << 4;
    }
    uint32_t bRow[4], bMask[4];
#pragma unroll
    for (int pp = 0; pp < 4; pp++) {
        int row = wn * 64 + pp * 16 + rowBl;
        bRow[pp] = row * 128;
        bMask[pp] = (row & 7) << 4;
    }

    float d[2][8][4];
#pragma unroll
    for (int ms = 0; ms < 2; ms++)
#pragma unroll
        for (int ns = 0; ns < 8; ns++)
#pragma unroll
            for (int j = 0; j < 4; j++) d[ms][ns][j] = 0.f;

    issue(0, 0);
    issue(1, 1);

    for (int c = 0; c < ENCH; c++) {
        int s = c % NSTG;
        CP_WAIT1();
        __syncthreads();
        if (c + 2 < ENCH) issue(c + 2, (c + 2) % NSTG);
        uint32_t bA = base + s * EST, bB = base + (NSTG + s) * EST;
#pragma unroll
        for (int kk = 0; kk < 4; kk++) {
            uint32_t kb = kk * 32;
            uint32_t af[2][4];
#pragma unroll
            for (int ms = 0; ms < 2; ms++)
                LDSM4(af[ms][0], af[ms][1], af[ms][2], af[ms][3],
                      bA + aRow[ms] + (((uint32_t)colAl + kb) ^ aMask[ms]));
            uint32_t bf[8][2];
#pragma unroll
            for (int pp = 0; pp < 4; pp++)
                LDSM4(bf[2 * pp][0], bf[2 * pp][1], bf[2 * pp + 1][0], bf[2 * pp + 1][1],
                      bB + bRow[pp] + (((uint32_t)colBl + kb) ^ bMask[pp]));
#pragma unroll
            for (int ms = 0; ms < 2; ms++)
#pragma unroll
                for (int ns = 0; ns < 8; ns++)
                    mma_f16(d[ms][ns], af[ms][0], af[ms][1], af[ms][2], af[ms][3],
                            bf[ns][0], bf[ns][1]);
        }
    }

#pragma unroll
    for (int ms = 0; ms < 2; ms++) {
        float pr0 = 0.f, pr1 = 0.f;
#pragma unroll
        for (int ns = 0; ns < 8; ns++) {
            int n0 = wn * 64 + ns * 8 + 2 * laneq;
            float q0 = qs[n0], q1 = qs[n0 + 1];
            pr0 += tanhf(d[ms][ns][0]) * q0 + tanhf(d[ms][ns][1]) * q1;
            pr1 += tanhf(d[ms][ns][2]) * q0 + tanhf(d[ms][ns][3]) * q1;
        }
#pragma unroll
        for (int o = 1; o < 4; o <<= 1) {
            pr0 += __shfl_xor_sync(0xffffffffu, pr0, o);
            pr1 += __shfl_xor_sync(0xffffffffu, pr1, o);
        }
        if (laneq == 0) {
            int r = wm * 32 + ms * 16 + lane4;
            red[wn * 128 + r] = pr0;
            red[wn * 128 + r + 8] = pr1;
        }
    }
    __syncthreads();
    if (tid < 128) {
        int t = t0 + tid;
        if (t < Tv)
            ebuf[(size_t)(b * Hv + h) * Tv + t] = red[tid] + red[128 + tid];
    }
}

// ---------------------------------------------------------------------------
// Masked softmax over T, in place.
// ---------------------------------------------------------------------------
__global__ __launch_bounds__(256) void softmax_kernel(float* __restrict__ wbuf,
                                                      const int* __restrict__ lens) {
    int bh = blockIdx.x;
    int b = bh / Hv;
    int len = get_len(lens, b);
    int tid = threadIdx.x;
    __shared__ float s[Tv];
    __shared__ float red[16];
    float* row = wbuf + (size_t)bh * Tv;
    for (int t = tid; t < Tv; t += 256) s[t] = row[t];
    __syncthreads();

    float m = -1e30f;
    for (int t = tid; t < len; t += 256) m = fmaxf(m, s[t]);
#pragma unroll
    for (int o = 16; o; o >>= 1) m = fmaxf(m, __shfl_xor_sync(0xffffffffu, m, o));
    if ((tid & 31) == 0) red[tid >> 5] = m;
    __syncthreads();
    m = red[0];
#pragma unroll
    for (int i = 1; i < 8; i++) m = fmaxf(m, red[i]);
    float M = SCALING * m;

    float lsum = 0.f;
    for (int t = tid; t < len; t += 256) lsum += expf(SCALING * s[t] - M);
#pragma unroll
    for (int o = 16; o; o >>= 1) lsum += __shfl_xor_sync(0xffffffffu, lsum, o);
    if ((tid & 31) == 0) red[8 + (tid >> 5)] = lsum;
    __syncthreads();
    float total = 0.f;
#pragma unroll
    for (int i = 0; i < 8; i++) total += red[8 + i];
    float inv = 1.f / total;

    for (int t = tid; t < Tv; t += 256)
        row[t] = (t < len) ? expf(SCALING * s[t] - M) * inv : 0.f;
}

// ---------------------------------------------------------------------------
// u partials: 512-thread CTAs; the two 256-thread halves split the 8 heads
// (4 each) over the SAME d-range -> acc[4][4]=16 regs/thread, ~2x occupancy.
// Duplicate enc16 loads between halves hit L1 (same sector). Per-(h,d)
// t-order identical to before -> bit-identical u.
// ---------------------------------------------------------------------------
__global__ __launch_bounds__(512) void u_kernel(const float* __restrict__ wbuf,
                                                const int* __restrict__ lens) {
    int tc = blockIdx.x, b = blockIdx.y;
    int hg = threadIdx.x >> 8;          // head group 0/1 -> heads hg*4..hg*4+3
    int d0 = (threadIdx.x & 255) * 4;
    int len = get_len(lens, b);
    int t0 = tc * TCW;
    float* up = g_up + (((size_t)b * Hv) * TCHUNK + tc) * Ev + d0;  // [b][h][tc][d]
    if (t0 >= len) {
#pragma unroll
        for (int hh = 0; hh < 4; hh++)
            *(float4*)(up + (size_t)(hg * 4 + hh) * TCHUNK * Ev) =
                make_float4(0.f, 0.f, 0.f, 0.f);
        return;
    }
    int tmax = min(min(TCW, Tv - t0), len - t0);
    __shared__ float ws[Hv][TCW];       // 4 KB
#pragma unroll
    for (int r = 0; r < 2; r++) {
        int f = r * 512 + threadIdx.x;  // 0..1023
        int h = f >> 7, tt = f & 127;
        int t = t0 + tt;
        ws[h][tt] = (t < Tv) ? wbuf[((size_t)(b * Hv + h)) * Tv + t] : 0.f;
    }
    __syncthreads();

    float acc[4][4];
#pragma unroll
    for (int hh = 0; hh < 4; hh++)
#pragma unroll
        for (int j = 0; j < 4; j++) acc[hh][j] = 0.f;

    const float* wsg = &ws[hg * 4][0];
    const __half* A = g_enc16 + (size_t)b * Tv * Ev + (size_t)t0 * Ev + d0;
#pragma unroll 4
    for (int tt = 0; tt < tmax; tt++) {
        uint2 raw = *(const uint2*)(A + (size_t)tt * Ev);
        float2 x01 = __half22float2(*(__half2*)&raw.x);
        float2 x23 = __half22float2(*(__half2*)&raw.y);
#pragma unroll
        for (int hh = 0; hh < 4; hh++) {
            float w = wsg[hh * TCW + tt];
            acc[hh][0] += w * x01.x;
            acc[hh][1] += w * x01.y;
            acc[hh][2] += w * x23.x;
            acc[hh][3] += w * x23.y;
        }
    }
#pragma unroll
    for (int hh = 0; hh < 4; hh++)
        *(float4*)(up + (size_t)(hg * 4 + hh) * TCHUNK * Ev) =
            make_float4(acc[hh][0], acc[hh][1], acc[hh][2], acc[hh][3]);
}

// ---------------------------------------------------------------------------
// c[b,h,v] = u[b,h,:]·Wv[h,:,v]; 256 thr: 2-way K split + smem combine.
// ---------------------------------------------------------------------------
__global__ __launch_bounds__(256) void c_kernel(const float* __restrict__ Wv) {
    int h = blockIdx.x, b = blockIdx.y;
    int half = threadIdx.x >> 7, v = threadIdx.x & 127;
    __shared__ float us[Ev];
    __shared__ float ps[2][DVv];
    const float* upb = g_up + ((size_t)(b * Hv + h)) * TCHUNK * Ev;
    for (int i = threadIdx.x; i < Ev; i += 256) {
        float s0 = 0.f, s1 = 0.f;
#pragma unroll
        for (int tc = 0; tc < TCHUNK; tc += 2) {
            s0 += upb[(size_t)tc * Ev + i];
            s1 += upb[(size_t)(tc + 1) * Ev + i];
        }
        us[i] = s0 + s1;
    }
    __syncthreads();
    const float* W = Wv + (size_t)h * Ev * DVv + v;
    int dbeg = half * 512;
    float a[4] = {0.f, 0.f, 0.f, 0.f};
#pragma unroll 4
    for (int d = dbeg; d < dbeg + 512; d += 4) {
        a[0] += us[d] * W[(size_t)d * DVv];
        a[1] += us[d + 1] * W[(size_t)(d + 1) * DVv];
        a[2] += us[d + 2] * W[(size_t)(d + 2) * DVv];
        a[3] += us[d + 3] * W[(size_t)(d + 3) * DVv];
    }
    ps[half][v] = (a[0] + a[1]) + (a[2] + a[3]);
    __syncthreads();
    if (threadIdx.x < DVv)
        g_c[(b * Hv + h) * DVv + threadIdx.x] = ps[0][threadIdx.x] + ps[1][threadIdx.x];
}

// ---------------------------------------------------------------------------
// out[b,e] = c_flat[b,:]·Wo[:,e]; 512 thr: 2-way K split + smem combine.
// ---------------------------------------------------------------------------
__global__ __launch_bounds__(512) void out_kernel(const float* __restrict__ Wo,
                                                  float* __restrict__ out) {
    int chunk = blockIdx.x, b = blockIdx.y;
    int half = threadIdx.x >> 8, el = threadIdx.x & 255;
    int e = chunk * 256 + el;
    __shared__ float cs[Hv * DVv];
    __shared__ float po[2][256];
    for (int i = threadIdx.x; i < Hv * DVv; i += 512) cs[i] = g_c[b * Hv * DVv + i];
    __syncthreads();
    int ibeg = half * 512;
    float a[4] = {0.f, 0.f, 0.f, 0.f};
#pragma unroll 4
    for (int i = ibeg; i < ibeg + 512; i += 4) {
        a[0] += cs[i] * Wo[(size_t)i * Ev + e];
        a[1] += cs[i + 1] * Wo[(size_t)(i + 1) * Ev + e];
        a[2] += cs[i + 2] * Wo[(size_t)(i + 2) * Ev + e];
        a[3] += cs[i + 3] * Wo[(size_t)(i + 3) * Ev + e];
    }
    po[half][el] = (a[0] + a[1]) + (a[2] + a[3]);
    __syncthreads();
    if (threadIdx.x < 256)
        out[(size_t)b * Ev + e] = po[0][el] + po[1][el];
}

// ---------------------------------------------------------------------------
extern "C" void kernel_launch(void* const* d_in, const int* in_sizes, int n_in,
                              void* d_out, int out_size) {
    const float* enc   = (const float*)d_in[0];
    const int*   lens  = (const int*)d_in[1];
    const float* dec_z = (const float*)d_in[2];
    const float* Wq    = (const float*)d_in[3];
    const float* bq    = (const float*)d_in[4];
    const float* Wk    = (const float*)d_in[5];
    const float* Wv    = (const float*)d_in[6];
    const float* Wo    = (const float*)d_in[7];

    float* out  = (float*)d_out;   // (B,E)
    float* wbuf = out + Bv * Ev;   // (B,H,T): e logits, then w in place

    static int inited = 0;
    if (!inited) {
        cudaFuncSetAttribute(e_tc_kernel, cudaFuncAttributeMaxDynamicSharedMemorySize, E_SMEM);
        inited = 1;
    }

    prep_kernel<<<PREPB, 256>>>(enc, lens, Wk, dec_z, Wq, bq);
    e_tc_kernel<<<dim3(Hv, (Tv + 127) / 128, Bv), 256, E_SMEM>>>(wbuf, lens);
    softmax_kernel<<<Bv * Hv, 256>>>(wbuf, lens);
    u_kernel<<<dim3(TCHUNK, Bv), 512>>>(wbuf, lens);
    c_kernel<<<dim3(Hv, Bv), 256>>>(Wv);
    out_kernel<<<dim3(Ev / 256, Bv), 512>>>(Wo, out);
}

// round 15
// speedup vs baseline: 1.2832x; 1.0211x over previous
#include <cuda_runtime.h>
#include <cuda_fp16.h>
#include <cstdint>

#define Bv 32
#define BH 16                          // batches per pipeline half
#define Tv 1500
#define Ev 1024
#define Hv 8
#define DKv 128
#define DVv 128
#define Dv 1024
#define SCALING 0.088388347648318447f  // 1/sqrt(128)
#define TCHUNK 12
#define TCW 128                        // t rows per u-chunk

// Scratch (no allocations allowed)
__device__ float g_q[Bv * Hv * DKv];            // tanh(dec_z@Wq + bq)
__device__ float g_c[Bv * Hv * DVv];            // u @ Wv
__device__ float g_up[(size_t)Bv * Hv * TCHUNK * Ev];  // u partials [b][h][tc][d]
__device__ __half g_enc16[(size_t)Bv * Tv * Ev];   // enc in fp16 (98.3 MB)
__device__ __half g_wkT16[(size_t)Hv * DKv * Ev];  // Wk^T in fp16: [h][n][e]

// ---------------------------------------------------------------------------
// PTX helpers (sm_80-level only; tcgen05 is rejected by this harness target)
// ---------------------------------------------------------------------------
__device__ __forceinline__ uint32_t smem_u32(const void* p) {
    uint32_t a;
    asm("{ .reg .u64 t; cvta.to.shared.u64 t, %1; cvt.u32.u64 %0, t; }" : "=r"(a) : "l"(p));
    return a;
}
#define CP16(sm, gm, sz) \
    asm volatile("cp.async.cg.shared.global [%0], [%1], 16, %2;" ::"r"(sm), "l"(gm), "r"(sz) : "memory")
#define CP_COMMIT() asm volatile("cp.async.commit_group;" ::: "memory")
#define CP_WAIT1() asm volatile("cp.async.wait_group 1;" ::: "memory")
#define LDSM4(r0, r1, r2, r3, a)                                             \
    asm volatile("ldmatrix.sync.aligned.m8n8.x4.shared.b16 {%0,%1,%2,%3}, [%4];" \
                 : "=r"(r0), "=r"(r1), "=r"(r2), "=r"(r3) : "r"(a))

__device__ __forceinline__ void mma_f16(float* d, uint32_t a0, uint32_t a1, uint32_t a2,
                                        uint32_t a3, uint32_t b0, uint32_t b1) {
    asm volatile(
        "mma.sync.aligned.m16n8k16.row.col.f32.f16.f16.f32 "
        "{%0,%1,%2,%3}, {%4,%5,%6,%7}, {%8,%9}, {%0,%1,%2,%3};"
        : "+f"(d[0]), "+f"(d[1]), "+f"(d[2]), "+f"(d[3])
        : "r"(a0), "r"(a1), "r"(a2), "r"(a3), "r"(b0), "r"(b1));
}
__device__ __forceinline__ uint32_t sw128(uint32_t o) { return o ^ ((o >> 3) & 0x70); }

// ---------------------------------------------------------------------------
// Length read with dtype sniff (int64 declared, int32 in practice)
// ---------------------------------------------------------------------------
__device__ __forceinline__ int get_len(const int* __restrict__ L, int b) {
    bool is64 = (L[1] == 0);
    return is64 ? L[2 * b] : L[b];
}

// ---------------------------------------------------------------------------
// Prep (per half): enc->fp16 for b in [b0,b0+BH); if b0==0 also WkT + q.
// ---------------------------------------------------------------------------
#define ENCBH ((BH * Tv * Ev) / (256 * 8))  // 12000
#define WKTB ((Ev / 32) * (DKv / 32) * Hv)  // 1024
#define QB ((Hv / 2) * Bv)                  // 128

__global__ __launch_bounds__(256) void prep_kernel(const float* __restrict__ enc,
                                                   const int* __restrict__ lens,
                                                   const float* __restrict__ Wk,
                                                   const float* __restrict__ dec_z,
                                                   const float* __restrict__ Wq,
                                                   const float* __restrict__ bq,
                                                   int b0) {
    int bx = blockIdx.x;
    if (bx < ENCBH) {
        size_t base = (size_t)b0 * Tv * Ev + ((size_t)bx * 256 + threadIdx.x) * 8;
        int t = (int)((base / Ev) % Tv);
        int b = (int)(base / ((size_t)Ev * Tv));
        int len = get_len(lens, b);
        if (t >= ((len + 127) & ~127)) return;
        float4 v0 = *(const float4*)(enc + base);
        float4 v1 = *(const float4*)(enc + base + 4);
        __half2 h[4];
        h[0] = __floats2half2_rn(v0.x, v0.y);
        h[1] = __floats2half2_rn(v0.z, v0.w);
        h[2] = __floats2half2_rn(v1.x, v1.y);
        h[3] = __floats2half2_rn(v1.z, v1.w);
        *(uint4*)(g_enc16 + base) = *(uint4*)h;
    } else if (bx < ENCBH + WKTB) {
        __shared__ float tile[32][33];
        int idx = bx - ENCBH;
        int e0 = (idx & 31) * 32;
        int n0 = ((idx >> 5) & 3) * 32;
        int h = idx >> 7;
        int tx = threadIdx.x & 31, ty = threadIdx.x >> 5;
        for (int i = ty; i < 32; i += 8)
            tile[i][tx] = Wk[((size_t)h * Ev + e0 + i) * DKv + n0 + tx];
        __syncthreads();
        for (int i = ty; i < 32; i += 8)
            g_wkT16[((size_t)h * DKv + n0 + i) * Ev + e0 + tx] = __float2half_rn(tile[tx][i]);
    } else {
        __shared__ float zs[Dv];
        int idx = bx - ENCBH - WKTB;
        int b = idx >> 2;
        int h = (idx & 3) * 2 + (threadIdx.x >> 7);
        int k = threadIdx.x & 127;
        for (int i = threadIdx.x; i < Dv; i += 256) zs[i] = dec_z[b * Dv + i];
        __syncthreads();
        const float* W = Wq + (size_t)h * Dv * DKv + k;
        float a[4] = {0.f, 0.f, 0.f, 0.f};
#pragma unroll 4
        for (int d = 0; d < Dv; d += 4) {
            a[0] += zs[d] * W[(size_t)d * DKv];
            a[1] += zs[d + 1] * W[(size_t)(d + 1) * DKv];
            a[2] += zs[d + 2] * W[(size_t)(d + 2) * DKv];
            a[3] += zs[d + 3] * W[(size_t)(d + 3) * DKv];
        }
        g_q[(b * Hv + h) * DKv + k] =
            tanhf(bq[h * DKv + k] + (a[0] + a[1]) + (a[2] + a[3]));
    }
}

// ---------------------------------------------------------------------------
// e[b,h,t]: fp16 m16n8k16 GEMM (128-t tile, 2 CTA/SM, 128 regs), per half.
// ---------------------------------------------------------------------------
#define ECH 64
#define ENCH (Ev / ECH)
#define EST 16384
#define NSTG 3
#define OFF_QS (2 * NSTG * EST)
#define OFF_RED (OFF_QS + 512)
#define E_SMEM (OFF_RED + 1024)

__global__ __launch_bounds__(256, 2) void e_tc_kernel(float* __restrict__ ebuf,
                                                      const int* __restrict__ lens,
                                                      int b0) {
    extern __shared__ __align__(16) char dsm[];
    float* qs = (float*)(dsm + OFF_QS);
    float* red = (float*)(dsm + OFF_RED);

    int tid = threadIdx.x, wid = tid >> 5, lane = tid & 31;
    int h = blockIdx.x, tile = blockIdx.y, b = blockIdx.z + b0;
    int t0 = tile * 128;
    int len = get_len(lens, b);
    if (t0 >= len) return;

    int wm = wid & 3, wn = wid >> 2;
    int lane4 = lane >> 2, laneq = lane & 3;

    if (tid < DKv) qs[tid] = g_q[(b * Hv + h) * DKv + tid];

    const __half* A = g_enc16 + (size_t)b * Tv * Ev;
    const __half* Wt = g_wkT16 + (size_t)h * DKv * Ev;

    uint32_t base = smem_u32(dsm);

    uint32_t swz[4];
    const __half* pA[4];
    const __half* pB[4];
    uint32_t szA[4];
#pragma unroll
    for (int r = 0; r < 4; r++) {
        int idx = r * 256 + tid;
        int row = idx >> 3, seg = idx & 7;
        swz[r] = sw128(row * 128 + seg * 16);
        int t = t0 + row;
        szA[r] = (t < Tv) ? 16u : 0u;
        pA[r] = A + (size_t)t * Ev + seg * 8;
        pB[r] = Wt + (size_t)row * Ev + seg * 8;
    }

    auto issue = [&](int c, int s) {
        int k0 = c * ECH;
        uint32_t bA = base + s * EST, bB = base + (NSTG + s) * EST;
#pragma unroll
        for (int r = 0; r < 4; r++) CP16(bA + swz[r], pA[r] + k0, szA[r]);
#pragma unroll
        for (int r = 0; r < 4; r++) CP16(bB + swz[r], pB[r] + k0, 16u);
        CP_COMMIT();
    };

    int rowAl = (lane & 7) + ((lane >> 3) & 1) * 8;
    int colAl = ((lane >> 4) & 1) * 16;
    int rowBl = (lane & 7) + ((lane >> 4) & 1) * 8;
    int colBl = ((lane >> 3) & 1) * 16;
    uint32_t aRow[2], aMask[2];
#pragma unroll
    for (int ms = 0; ms < 2; ms++) {
        int row = wm * 32 + ms * 16 + rowAl;
        aRow[ms] = row * 128;
        aMask[ms] = (row & 7) << 4;
    }
    uint32_t bRow[4], bMask[4];
#pragma unroll
    for (int pp = 0; pp < 4; pp++) {
        int row = wn * 64 + pp * 16 + rowBl;
        bRow[pp] = row * 128;
        bMask[pp] = (row & 7) << 4;
    }

    float d[2][8][4];
#pragma unroll
    for (int ms = 0; ms < 2; ms++)
#pragma unroll
        for (int ns = 0; ns < 8; ns++)
#pragma unroll
            for (int j = 0; j < 4; j++) d[ms][ns][j] = 0.f;

    issue(0, 0);
    issue(1, 1);

    for (int c = 0; c < ENCH; c++) {
        int s = c % NSTG;
        CP_WAIT1();
        __syncthreads();
        if (c + 2 < ENCH) issue(c + 2, (c + 2) % NSTG);
        uint32_t bA = base + s * EST, bB = base + (NSTG + s) * EST;
#pragma unroll
        for (int kk = 0; kk < 4; kk++) {
            uint32_t kb = kk * 32;
            uint32_t af[2][4];
#pragma unroll
            for (int ms = 0; ms < 2; ms++)
                LDSM4(af[ms][0], af[ms][1], af[ms][2], af[ms][3],
                      bA + aRow[ms] + (((uint32_t)colAl + kb) ^ aMask[ms]));
            uint32_t bf[8][2];
#pragma unroll
            for (int pp = 0; pp < 4; pp++)
                LDSM4(bf[2 * pp][0], bf[2 * pp][1], bf[2 * pp + 1][0], bf[2 * pp + 1][1],
                      bB + bRow[pp] + (((uint32_t)colBl + kb) ^ bMask[pp]));
#pragma unroll
            for (int ms = 0; ms < 2; ms++)
#pragma unroll
                for (int ns = 0; ns < 8; ns++)
                    mma_f16(d[ms][ns], af[ms][0], af[ms][1], af[ms][2], af[ms][3],
                            bf[ns][0], bf[ns][1]);
        }
    }

#pragma unroll
    for (int ms = 0; ms < 2; ms++) {
        float pr0 = 0.f, pr1 = 0.f;
#pragma unroll
        for (int ns = 0; ns < 8; ns++) {
            int n0 = wn * 64 + ns * 8 + 2 * laneq;
            float q0 = qs[n0], q1 = qs[n0 + 1];
            pr0 += tanhf(d[ms][ns][0]) * q0 + tanhf(d[ms][ns][1]) * q1;
            pr1 += tanhf(d[ms][ns][2]) * q0 + tanhf(d[ms][ns][3]) * q1;
        }
#pragma unroll
        for (int o = 1; o < 4; o <<= 1) {
            pr0 += __shfl_xor_sync(0xffffffffu, pr0, o);
            pr1 += __shfl_xor_sync(0xffffffffu, pr1, o);
        }
        if (laneq == 0) {
            int r = wm * 32 + ms * 16 + lane4;
            red[wn * 128 + r] = pr0;
            red[wn * 128 + r + 8] = pr1;
        }
    }
    __syncthreads();
    if (tid < 128) {
        int t = t0 + tid;
        if (t < Tv)
            ebuf[(size_t)(b * Hv + h) * Tv + t] = red[tid] + red[128 + tid];
    }
}

// ---------------------------------------------------------------------------
// Masked softmax over T, in place, per half.
// ---------------------------------------------------------------------------
__global__ __launch_bounds__(256) void softmax_kernel(float* __restrict__ wbuf,
                                                      const int* __restrict__ lens,
                                                      int b0) {
    int bh = blockIdx.x + b0 * Hv;
    int b = bh / Hv;
    int len = get_len(lens, b);
    int tid = threadIdx.x;
    __shared__ float s[Tv];
    __shared__ float red[16];
    float* row = wbuf + (size_t)bh * Tv;
    for (int t = tid; t < Tv; t += 256) s[t] = row[t];
    __syncthreads();

    float m = -1e30f;
    for (int t = tid; t < len; t += 256) m = fmaxf(m, s[t]);
#pragma unroll
    for (int o = 16; o; o >>= 1) m = fmaxf(m, __shfl_xor_sync(0xffffffffu, m, o));
    if ((tid & 31) == 0) red[tid >> 5] = m;
    __syncthreads();
    m = red[0];
#pragma unroll
    for (int i = 1; i < 8; i++) m = fmaxf(m, red[i]);
    float M = SCALING * m;

    float lsum = 0.f;
    for (int t = tid; t < len; t += 256) lsum += expf(SCALING * s[t] - M);
#pragma unroll
    for (int o = 16; o; o >>= 1) lsum += __shfl_xor_sync(0xffffffffu, lsum, o);
    if ((tid & 31) == 0) red[8 + (tid >> 5)] = lsum;
    __syncthreads();
    float total = 0.f;
#pragma unroll
    for (int i = 0; i < 8; i++) total += red[8 + i];
    float inv = 1.f / total;

    for (int t = tid; t < Tv; t += 256)
        row[t] = (t < len) ? expf(SCALING * s[t] - M) * inv : 0.f;
}

// ---------------------------------------------------------------------------
// u partials: 512-thread CTAs, head-split halves (R14 config), per half.
// ---------------------------------------------------------------------------
__global__ __launch_bounds__(512) void u_kernel(const float* __restrict__ wbuf,
                                                const int* __restrict__ lens,
                                                int b0) {
    int tc = blockIdx.x, b = blockIdx.y + b0;
    int hg = threadIdx.x >> 8;
    int d0 = (threadIdx.x & 255) * 4;
    int len = get_len(lens, b);
    int t0 = tc * TCW;
    float* up = g_up + (((size_t)b * Hv) * TCHUNK + tc) * Ev + d0;
    if (t0 >= len) {
#pragma unroll
        for (int hh = 0; hh < 4; hh++)
            *(float4*)(up + (size_t)(hg * 4 + hh) * TCHUNK * Ev) =
                make_float4(0.f, 0.f, 0.f, 0.f);
        return;
    }
    int tmax = min(min(TCW, Tv - t0), len - t0);
    __shared__ float ws[Hv][TCW];
#pragma unroll
    for (int r = 0; r < 2; r++) {
        int f = r * 512 + threadIdx.x;
        int h = f >> 7, tt = f & 127;
        int t = t0 + tt;
        ws[h][tt] = (t < Tv) ? wbuf[((size_t)(b * Hv + h)) * Tv + t] : 0.f;
    }
    __syncthreads();

    float acc[4][4];
#pragma unroll
    for (int hh = 0; hh < 4; hh++)
#pragma unroll
        for (int j = 0; j < 4; j++) acc[hh][j] = 0.f;

    const float* wsg = &ws[hg * 4][0];
    const __half* A = g_enc16 + (size_t)b * Tv * Ev + (size_t)t0 * Ev + d0;
#pragma unroll 4
    for (int tt = 0; tt < tmax; tt++) {
        uint2 raw = *(const uint2*)(A + (size_t)tt * Ev);
        float2 x01 = __half22float2(*(__half2*)&raw.x);
        float2 x23 = __half22float2(*(__half2*)&raw.y);
#pragma unroll
        for (int hh = 0; hh < 4; hh++) {
            float w = wsg[hh * TCW + tt];
            acc[hh][0] += w * x01.x;
            acc[hh][1] += w * x01.y;
            acc[hh][2] += w * x23.x;
            acc[hh][3] += w * x23.y;
        }
    }
#pragma unroll
    for (int hh = 0; hh < 4; hh++)
        *(float4*)(up + (size_t)(hg * 4 + hh) * TCHUNK * Ev) =
            make_float4(acc[hh][0], acc[hh][1], acc[hh][2], acc[hh][3]);
}

// ---------------------------------------------------------------------------
// c[b,h,v] = u[b,h,:]·Wv[h,:,v]; 2-way K split + smem combine, per half.
// ---------------------------------------------------------------------------
__global__ __launch_bounds__(256) void c_kernel(const float* __restrict__ Wv, int b0) {
    int h = blockIdx.x, b = blockIdx.y + b0;
    int half = threadIdx.x >> 7, v = threadIdx.x & 127;
    __shared__ float us[Ev];
    __shared__ float ps[2][DVv];
    const float* upb = g_up + ((size_t)(b * Hv + h)) * TCHUNK * Ev;
    for (int i = threadIdx.x; i < Ev; i += 256) {
        float s0 = 0.f, s1 = 0.f;
#pragma unroll
        for (int tc = 0; tc < TCHUNK; tc += 2) {
            s0 += upb[(size_t)tc * Ev + i];
            s1 += upb[(size_t)(tc + 1) * Ev + i];
        }
        us[i] = s0 + s1;
    }
    __syncthreads();
    const float* W = Wv + (size_t)h * Ev * DVv + v;
    int dbeg = half * 512;
    float a[4] = {0.f, 0.f, 0.f, 0.f};
#pragma unroll 4
    for (int d = dbeg; d < dbeg + 512; d += 4) {
        a[0] += us[d] * W[(size_t)d * DVv];
        a[1] += us[d + 1] * W[(size_t)(d + 1) * DVv];
        a[2] += us[d + 2] * W[(size_t)(d + 2) * DVv];
        a[3] += us[d + 3] * W[(size_t)(d + 3) * DVv];
    }
    ps[half][v] = (a[0] + a[1]) + (a[2] + a[3]);
    __syncthreads();
    if (threadIdx.x < DVv)
        g_c[(b * Hv + h) * DVv + threadIdx.x] = ps[0][threadIdx.x] + ps[1][threadIdx.x];
}

// ---------------------------------------------------------------------------
// out[b,e] = c_flat[b,:]·Wo[:,e]; 2-way K split + smem combine, per half.
// ---------------------------------------------------------------------------
__global__ __launch_bounds__(512) void out_kernel(const float* __restrict__ Wo,
                                                  float* __restrict__ out, int b0) {
    int chunk = blockIdx.x, b = blockIdx.y + b0;
    int half = threadIdx.x >> 8, el = threadIdx.x & 255;
    int e = chunk * 256 + el;
    __shared__ float cs[Hv * DVv];
    __shared__ float po[2][256];
    for (int i = threadIdx.x; i < Hv * DVv; i += 512) cs[i] = g_c[b * Hv * DVv + i];
    __syncthreads();
    int ibeg = half * 512;
    float a[4] = {0.f, 0.f, 0.f, 0.f};
#pragma unroll 4
    for (int i = ibeg; i < ibeg + 512; i += 4) {
        a[0] += cs[i] * Wo[(size_t)i * Ev + e];
        a[1] += cs[i + 1] * Wo[(size_t)(i + 1) * Ev + e];
        a[2] += cs[i + 2] * Wo[(size_t)(i + 2) * Ev + e];
        a[3] += cs[i + 3] * Wo[(size_t)(i + 3) * Ev + e];
    }
    po[half][el] = (a[0] + a[1]) + (a[2] + a[3]);
    __syncthreads();
    if (threadIdx.x < 256)
        out[(size_t)b * Ev + e] = po[0][el] + po[1][el];
}

// ---------------------------------------------------------------------------
extern "C" void kernel_launch(void* const* d_in, const int* in_sizes, int n_in,
                              void* d_out, int out_size) {
    const float* enc   = (const float*)d_in[0];
    const int*   lens  = (const int*)d_in[1];
    const float* dec_z = (const float*)d_in[2];
    const float* Wq    = (const float*)d_in[3];
    const float* bq    = (const float*)d_in[4];
    const float* Wk    = (const float*)d_in[5];
    const float* Wv    = (const float*)d_in[6];
    const float* Wo    = (const float*)d_in[7];

    float* out  = (float*)d_out;   // (B,E)
    float* wbuf = out + Bv * Ev;   // (B,H,T): e logits, then w in place

    static cudaStream_t s1 = nullptr;
    static cudaEvent_t evPA = nullptr, evB = nullptr;
    static int inited = 0;
    if (!inited) {
        cudaFuncSetAttribute(e_tc_kernel, cudaFuncAttributeMaxDynamicSharedMemorySize, E_SMEM);
        cudaStreamCreateWithFlags(&s1, cudaStreamNonBlocking);
        cudaEventCreateWithFlags(&evPA, cudaEventDisableTiming);
        cudaEventCreateWithFlags(&evB, cudaEventDisableTiming);
        inited = 1;
    }

    // Half A on stream 0 (origin): prepA includes wkT + q.
    prep_kernel<<<ENCBH + WKTB + QB, 256>>>(enc, lens, Wk, dec_z, Wq, bq, 0);
    cudaEventRecord(evPA, 0);

    e_tc_kernel<<<dim3(Hv, (Tv + 127) / 128, BH), 256, E_SMEM>>>(wbuf, lens, 0);
    softmax_kernel<<<BH * Hv, 256>>>(wbuf, lens, 0);
    u_kernel<<<dim3(TCHUNK, BH), 512>>>(wbuf, lens, 0);
    c_kernel<<<dim3(Hv, BH), 256>>>(Wv, 0);
    out_kernel<<<dim3(Ev / 256, BH), 512>>>(Wo, out, 0);

    // Half B on stream 1: waits weights+qA ready, runs under half A's e.
    cudaStreamWaitEvent(s1, evPA, 0);
    prep_kernel<<<ENCBH, 256, 0, s1>>>(enc, lens, Wk, dec_z, Wq, bq, BH);
    e_tc_kernel<<<dim3(Hv, (Tv + 127) / 128, BH), 256, E_SMEM, s1>>>(wbuf, lens, BH);
    softmax_kernel<<<BH * Hv, 256, 0, s1>>>(wbuf, lens, BH);
    u_kernel<<<dim3(TCHUNK, BH), 512, 0, s1>>>(wbuf, lens, BH);
    c_kernel<<<dim3(Hv, BH), 256, 0, s1>>>(Wv, BH);
    out_kernel<<<dim3(Ev / 256, BH), 512, 0, s1>>>(Wo, out, BH);
    cudaEventRecord(evB, s1);

    // Join: all of half B must complete before the graph's end on stream 0.
    cudaStreamWaitEvent(0, evB, 0);
}